// round 1
// baseline (speedup 1.0000x reference)
#include <cuda_runtime.h>
#include <cuda_bf16.h>
#include <stdint.h>

#define NNODES 100000
#define H1DIM 128
#define H2DIM 64
#define BN_EPS 1e-5f

// ---------------- scratch (device globals: allocation-guard safe) ----------------
__device__ float g_deg[NNODES];
__device__ float g_dinv[NNODES];
__device__ float g_h1[(size_t)NNODES * H1DIM];    // x @ W1
__device__ float g_agg1[(size_t)NNODES * H1DIM];  // aggregated layer-1 (pre-BN, pre-b1; b1 folded into BN shift)
__device__ float g_h2[(size_t)NNODES * H2DIM];    // bnrelu(agg1) @ W2
__device__ float g_bns[H1DIM];                    // BN scale  = gamma * rsqrt(var+eps)
__device__ float g_bnt[H1DIM];                    // BN shift  = (b1 - rmean)*scale + beta
__device__ int   g_is64;                          // edge_index dtype flag

// ---------------- edge index dtype detection ----------------
__global__ void detect_idx_kernel(const void* ei) {
    if (threadIdx.x == 0 && blockIdx.x == 0) {
        const long long* p = (const long long*)ei;
        int is64 = 1;
        for (int i = 0; i < 64; i++) {
            long long v = p[i];
            if (v < 0 || v >= (long long)NNODES) { is64 = 0; break; }
        }
        g_is64 = is64;
    }
}

__device__ __forceinline__ int ld_idx(const void* p, long long i) {
    if (g_is64) return (int)((const long long*)p)[i];
    return ((const int*)p)[i];
}

// ---------------- degree / dinv / BN coeffs ----------------
__global__ void deg_init_kernel() {
    int i = blockIdx.x * blockDim.x + threadIdx.x;
    if (i < NNODES) g_deg[i] = 1.0f;  // self loop
}

__global__ void deg_count_kernel(const void* ei, int E) {
    int e = blockIdx.x * blockDim.x + threadIdx.x;
    if (e < E) {
        int d = ld_idx(ei, (long long)E + e);
        atomicAdd(&g_deg[d], 1.0f);
    }
}

__global__ void dinv_bn_kernel(const float* __restrict__ b1,
                               const float* __restrict__ gamma,
                               const float* __restrict__ beta,
                               const float* __restrict__ rmean,
                               const float* __restrict__ rvar) {
    int i = blockIdx.x * blockDim.x + threadIdx.x;
    if (i < NNODES) g_dinv[i] = rsqrtf(g_deg[i]);
    if (i < H1DIM) {
        float s = gamma[i] * rsqrtf(rvar[i] + BN_EPS);
        g_bns[i] = s;
        g_bnt[i] = (b1[i] - rmean[i]) * s + beta[i];
    }
}

// ---------------- GEMM1: h1 = x @ W1 ; agg1 = h1 * dinv^2 (self-loop init) ----------------
// 64 rows/block, N=128, K=128. 256 threads, 8x4 outputs/thread.
__global__ void __launch_bounds__(256) gemm1_kernel(const float* __restrict__ x,
                                                    const float* __restrict__ W) {
    extern __shared__ float smem[];
    float* sA = smem;              // 64*128
    float* sW = smem + 64 * 128;   // 128*128
    const int tid = threadIdx.x;
    const int row0 = blockIdx.x * 64;

    // load W (128x128) — whole K
    for (int i = tid; i < 128 * 128 / 4; i += 256)
        ((float4*)sW)[i] = ((const float4*)W)[i];
    // load A tile (64x128)
    for (int i = tid; i < 64 * 128 / 4; i += 256) {
        int r = i >> 5;
        int gr = row0 + r;
        float4 v = make_float4(0.f, 0.f, 0.f, 0.f);
        if (gr < NNODES) v = ((const float4*)x)[(size_t)gr * 32 + (i & 31)];
        ((float4*)sA)[i] = v;
    }
    __syncthreads();

    const int tx = tid & 31, ty = tid >> 5;
    const int r0 = ty * 8, c0 = tx * 4;
    float acc[8][4];
#pragma unroll
    for (int i = 0; i < 8; i++)
#pragma unroll
        for (int j = 0; j < 4; j++) acc[i][j] = 0.f;

    for (int k = 0; k < 128; k += 4) {
        float4 wv[4];
#pragma unroll
        for (int kk = 0; kk < 4; kk++)
            wv[kk] = *(const float4*)&sW[(k + kk) * 128 + c0];
#pragma unroll
        for (int i = 0; i < 8; i++) {
            float4 av = *(const float4*)&sA[(r0 + i) * 128 + k];
            acc[i][0] += av.x * wv[0].x + av.y * wv[1].x + av.z * wv[2].x + av.w * wv[3].x;
            acc[i][1] += av.x * wv[0].y + av.y * wv[1].y + av.z * wv[2].y + av.w * wv[3].y;
            acc[i][2] += av.x * wv[0].z + av.y * wv[1].z + av.z * wv[2].z + av.w * wv[3].z;
            acc[i][3] += av.x * wv[0].w + av.y * wv[1].w + av.z * wv[2].w + av.w * wv[3].w;
        }
    }

#pragma unroll
    for (int i = 0; i < 8; i++) {
        int gr = row0 + r0 + i;
        if (gr < NNODES) {
            float di = g_dinv[gr];
            float d2 = di * di;
            float4 h = make_float4(acc[i][0], acc[i][1], acc[i][2], acc[i][3]);
            *(float4*)&g_h1[(size_t)gr * 128 + c0] = h;
            float4 ag = make_float4(h.x * d2, h.y * d2, h.z * d2, h.w * d2);
            *(float4*)&g_agg1[(size_t)gr * 128 + c0] = ag;
        }
    }
}

// ---------------- scatter layer 1: agg1[dst] += h1[src] * dinv[s]*dinv[d] ----------------
__global__ void scatter1_kernel(const void* __restrict__ ei, int E) {
    int gw = (blockIdx.x * blockDim.x + threadIdx.x) >> 5;
    int lane = threadIdx.x & 31;
    if (gw >= E) return;
    int s = 0, d = 0;
    float norm = 0.f;
    if (lane == 0) {
        s = ld_idx(ei, gw);
        d = ld_idx(ei, (long long)E + gw);
        norm = g_dinv[s] * g_dinv[d];
    }
    s = __shfl_sync(0xFFFFFFFFu, s, 0);
    d = __shfl_sync(0xFFFFFFFFu, d, 0);
    norm = __shfl_sync(0xFFFFFFFFu, norm, 0);

    float4 v = *(const float4*)&g_h1[(size_t)s * 128 + lane * 4];
    float* out = &g_agg1[(size_t)d * 128 + lane * 4];
    atomicAdd(out + 0, v.x * norm);
    atomicAdd(out + 1, v.y * norm);
    atomicAdd(out + 2, v.z * norm);
    atomicAdd(out + 3, v.w * norm);
}

// ---------------- GEMM2: h2 = bnrelu(agg1) @ W2 ; out = h2 * dinv^2 + b2 ----------------
// 64 rows/block, N=64, K=128. 256 threads, 8x2 outputs/thread. BN+ReLU applied on A-tile load.
__global__ void __launch_bounds__(256) gemm2_kernel(const float* __restrict__ W,
                                                    const float* __restrict__ b2,
                                                    float* __restrict__ out) {
    extern __shared__ float smem[];
    float* sA = smem;              // 64*128
    float* sW = smem + 64 * 128;   // 128*64
    const int tid = threadIdx.x;
    const int row0 = blockIdx.x * 64;

    // load W2 (128x64)
    for (int i = tid; i < 128 * 64 / 4; i += 256)
        ((float4*)sW)[i] = ((const float4*)W)[i];
    // load A tile with BN + ReLU
    for (int i = tid; i < 64 * 128 / 4; i += 256) {
        int r = i >> 5;
        int c4 = i & 31;
        int gr = row0 + r;
        float4 v = make_float4(0.f, 0.f, 0.f, 0.f);
        if (gr < NNODES) {
            float4 raw = *(const float4*)&g_agg1[(size_t)gr * 128 + c4 * 4];
            float4 sv = *(const float4*)&g_bns[c4 * 4];
            float4 tv = *(const float4*)&g_bnt[c4 * 4];
            v.x = fmaxf(raw.x * sv.x + tv.x, 0.f);
            v.y = fmaxf(raw.y * sv.y + tv.y, 0.f);
            v.z = fmaxf(raw.z * sv.z + tv.z, 0.f);
            v.w = fmaxf(raw.w * sv.w + tv.w, 0.f);
        }
        ((float4*)sA)[i] = v;
    }
    __syncthreads();

    const int tx = tid & 31, ty = tid >> 5;
    const int r0 = ty * 8, c0 = tx * 2;
    float acc[8][2];
#pragma unroll
    for (int i = 0; i < 8; i++) { acc[i][0] = 0.f; acc[i][1] = 0.f; }

    for (int k = 0; k < 128; k += 4) {
        float2 wv[4];
#pragma unroll
        for (int kk = 0; kk < 4; kk++)
            wv[kk] = *(const float2*)&sW[(k + kk) * 64 + c0];
#pragma unroll
        for (int i = 0; i < 8; i++) {
            float4 av = *(const float4*)&sA[(r0 + i) * 128 + k];
            acc[i][0] += av.x * wv[0].x + av.y * wv[1].x + av.z * wv[2].x + av.w * wv[3].x;
            acc[i][1] += av.x * wv[0].y + av.y * wv[1].y + av.z * wv[2].y + av.w * wv[3].y;
        }
    }

    float bx = b2[c0], by = b2[c0 + 1];
#pragma unroll
    for (int i = 0; i < 8; i++) {
        int gr = row0 + r0 + i;
        if (gr < NNODES) {
            float di = g_dinv[gr];
            float d2 = di * di;
            float2 h = make_float2(acc[i][0], acc[i][1]);
            *(float2*)&g_h2[(size_t)gr * 64 + c0] = h;
            float2 o = make_float2(h.x * d2 + bx, h.y * d2 + by);
            *(float2*)&out[(size_t)gr * 64 + c0] = o;
        }
    }
}

// ---------------- scatter layer 2: out[dst] += h2[src] * dinv[s]*dinv[d] ----------------
__global__ void scatter2_kernel(const void* __restrict__ ei, int E, float* __restrict__ out) {
    int gw = (blockIdx.x * blockDim.x + threadIdx.x) >> 5;
    int lane = threadIdx.x & 31;
    if (gw >= E) return;
    int s = 0, d = 0;
    float norm = 0.f;
    if (lane == 0) {
        s = ld_idx(ei, gw);
        d = ld_idx(ei, (long long)E + gw);
        norm = g_dinv[s] * g_dinv[d];
    }
    s = __shfl_sync(0xFFFFFFFFu, s, 0);
    d = __shfl_sync(0xFFFFFFFFu, d, 0);
    norm = __shfl_sync(0xFFFFFFFFu, norm, 0);

    float2 v = *(const float2*)&g_h2[(size_t)s * 64 + lane * 2];
    float* dst = &out[(size_t)d * 64 + lane * 2];
    atomicAdd(dst + 0, v.x * norm);
    atomicAdd(dst + 1, v.y * norm);
}

// ---------------- launch ----------------
extern "C" void kernel_launch(void* const* d_in, const int* in_sizes, int n_in,
                              void* d_out, int out_size) {
    const float* x     = (const float*)d_in[0];
    const void*  ei    = d_in[1];
    const float* W1    = (const float*)d_in[2];
    const float* b1    = (const float*)d_in[3];
    const float* gamma = (const float*)d_in[4];
    const float* beta  = (const float*)d_in[5];
    const float* rmean = (const float*)d_in[6];
    const float* rvar  = (const float*)d_in[7];
    const float* W2    = (const float*)d_in[8];
    const float* b2    = (const float*)d_in[9];
    float* out = (float*)d_out;

    const int E = in_sizes[1] / 2;

    cudaFuncSetAttribute(gemm1_kernel, cudaFuncAttributeMaxDynamicSharedMemorySize, 96 * 1024);
    cudaFuncSetAttribute(gemm2_kernel, cudaFuncAttributeMaxDynamicSharedMemorySize, 64 * 1024);

    detect_idx_kernel<<<1, 1>>>(ei);

    int nblk = (NNODES + 255) / 256;
    deg_init_kernel<<<nblk, 256>>>();
    deg_count_kernel<<<(E + 255) / 256, 256>>>(ei, E);
    dinv_bn_kernel<<<nblk, 256>>>(b1, gamma, beta, rmean, rvar);

    int gblk = (NNODES + 63) / 64;
    gemm1_kernel<<<gblk, 256, 96 * 1024>>>(x, W1);

    long long sthreads = (long long)E * 32;
    int sblk = (int)((sthreads + 255) / 256);
    scatter1_kernel<<<sblk, 256>>>(ei, E);

    gemm2_kernel<<<gblk, 256, 64 * 1024>>>(W2, b2, out);

    scatter2_kernel<<<sblk, 256>>>(ei, E, out);
}

// round 2
// speedup vs baseline: 1.3298x; 1.3298x over previous
#include <cuda_runtime.h>
#include <cuda_bf16.h>
#include <stdint.h>

#define NNODES 100000
#define H1DIM 128
#define H2DIM 64
#define BN_EPS 1e-5f

// ---------------- scratch (device globals: allocation-guard safe) ----------------
__device__ float g_deg[NNODES];
__device__ float g_dinv[NNODES];
__device__ float g_h1[(size_t)NNODES * H1DIM];    // x @ W1
__device__ float g_agg1[(size_t)NNODES * H1DIM];  // aggregated layer-1
__device__ float g_h2[(size_t)NNODES * H2DIM];    // bnrelu(agg1) @ W2
__device__ float g_bns[H1DIM];                    // BN scale
__device__ float g_bnt[H1DIM];                    // BN shift (absorbs b1)
__device__ int   g_is64;                          // edge_index dtype flag

// ---------------- vectorized reduction (sm_90+: red.global.add.v4.f32) ----------------
__device__ __forceinline__ void red_add_v4(float* p, float4 v) {
    asm volatile("red.global.add.v4.f32 [%0], {%1, %2, %3, %4};"
                 :: "l"(p), "f"(v.x), "f"(v.y), "f"(v.z), "f"(v.w)
                 : "memory");
}

// ---------------- edge index dtype detection ----------------
__global__ void detect_idx_kernel(const void* ei) {
    if (threadIdx.x == 0 && blockIdx.x == 0) {
        const long long* p = (const long long*)ei;
        int is64 = 1;
        for (int i = 0; i < 64; i++) {
            long long v = p[i];
            if (v < 0 || v >= (long long)NNODES) { is64 = 0; break; }
        }
        g_is64 = is64;
    }
}

__device__ __forceinline__ int ld_idx(const void* p, long long i) {
    if (g_is64) return (int)((const long long*)p)[i];
    return ((const int*)p)[i];
}

// ---------------- degree / dinv / BN coeffs ----------------
__global__ void deg_init_kernel() {
    int i = blockIdx.x * blockDim.x + threadIdx.x;
    if (i < NNODES) g_deg[i] = 1.0f;  // self loop
}

__global__ void deg_count_kernel(const void* ei, int E) {
    int e = blockIdx.x * blockDim.x + threadIdx.x;
    if (e < E) {
        int d = ld_idx(ei, (long long)E + e);
        atomicAdd(&g_deg[d], 1.0f);
    }
}

__global__ void dinv_bn_kernel(const float* __restrict__ b1,
                               const float* __restrict__ gamma,
                               const float* __restrict__ beta,
                               const float* __restrict__ rmean,
                               const float* __restrict__ rvar) {
    int i = blockIdx.x * blockDim.x + threadIdx.x;
    if (i < NNODES) g_dinv[i] = rsqrtf(g_deg[i]);
    if (i < H1DIM) {
        float s = gamma[i] * rsqrtf(rvar[i] + BN_EPS);
        g_bns[i] = s;
        g_bnt[i] = (b1[i] - rmean[i]) * s + beta[i];
    }
}

// ---------------- GEMM1: h1 = x @ W1 ; agg1 = h1 * dinv^2 (self-loop init) ----------------
__global__ void __launch_bounds__(256) gemm1_kernel(const float* __restrict__ x,
                                                    const float* __restrict__ W) {
    extern __shared__ float smem[];
    float* sA = smem;              // 64*128
    float* sW = smem + 64 * 128;   // 128*128
    const int tid = threadIdx.x;
    const int row0 = blockIdx.x * 64;

    for (int i = tid; i < 128 * 128 / 4; i += 256)
        ((float4*)sW)[i] = ((const float4*)W)[i];
    for (int i = tid; i < 64 * 128 / 4; i += 256) {
        int r = i >> 5;
        int gr = row0 + r;
        float4 v = make_float4(0.f, 0.f, 0.f, 0.f);
        if (gr < NNODES) v = ((const float4*)x)[(size_t)gr * 32 + (i & 31)];
        ((float4*)sA)[i] = v;
    }
    __syncthreads();

    const int tx = tid & 31, ty = tid >> 5;
    const int r0 = ty * 8, c0 = tx * 4;
    float acc[8][4];
#pragma unroll
    for (int i = 0; i < 8; i++)
#pragma unroll
        for (int j = 0; j < 4; j++) acc[i][j] = 0.f;

    for (int k = 0; k < 128; k += 4) {
        float4 wv[4];
#pragma unroll
        for (int kk = 0; kk < 4; kk++)
            wv[kk] = *(const float4*)&sW[(k + kk) * 128 + c0];
#pragma unroll
        for (int i = 0; i < 8; i++) {
            float4 av = *(const float4*)&sA[(r0 + i) * 128 + k];
            acc[i][0] += av.x * wv[0].x + av.y * wv[1].x + av.z * wv[2].x + av.w * wv[3].x;
            acc[i][1] += av.x * wv[0].y + av.y * wv[1].y + av.z * wv[2].y + av.w * wv[3].y;
            acc[i][2] += av.x * wv[0].z + av.y * wv[1].z + av.z * wv[2].z + av.w * wv[3].z;
            acc[i][3] += av.x * wv[0].w + av.y * wv[1].w + av.z * wv[2].w + av.w * wv[3].w;
        }
    }

#pragma unroll
    for (int i = 0; i < 8; i++) {
        int gr = row0 + r0 + i;
        if (gr < NNODES) {
            float di = g_dinv[gr];
            float d2 = di * di;
            float4 h = make_float4(acc[i][0], acc[i][1], acc[i][2], acc[i][3]);
            *(float4*)&g_h1[(size_t)gr * 128 + c0] = h;
            float4 ag = make_float4(h.x * d2, h.y * d2, h.z * d2, h.w * d2);
            *(float4*)&g_agg1[(size_t)gr * 128 + c0] = ag;
        }
    }
}

// ---------------- scatter layer 1: one warp per edge, 32 x v4 RED ----------------
__global__ void scatter1_kernel(const void* __restrict__ ei, int E) {
    int gw = (blockIdx.x * blockDim.x + threadIdx.x) >> 5;
    int lane = threadIdx.x & 31;
    if (gw >= E) return;
    int s = 0, d = 0;
    float norm = 0.f;
    if (lane == 0) {
        s = ld_idx(ei, gw);
        d = ld_idx(ei, (long long)E + gw);
        norm = g_dinv[s] * g_dinv[d];
    }
    s = __shfl_sync(0xFFFFFFFFu, s, 0);
    d = __shfl_sync(0xFFFFFFFFu, d, 0);
    norm = __shfl_sync(0xFFFFFFFFu, norm, 0);

    float4 v = *(const float4*)&g_h1[(size_t)s * 128 + lane * 4];
    red_add_v4(&g_agg1[(size_t)d * 128 + lane * 4],
               make_float4(v.x * norm, v.y * norm, v.z * norm, v.w * norm));
}

// ---------------- GEMM2: h2 = bnrelu(agg1) @ W2 ; out = h2 * dinv^2 + b2 ----------------
__global__ void __launch_bounds__(256) gemm2_kernel(const float* __restrict__ W,
                                                    const float* __restrict__ b2,
                                                    float* __restrict__ out) {
    extern __shared__ float smem[];
    float* sA = smem;              // 64*128
    float* sW = smem + 64 * 128;   // 128*64
    const int tid = threadIdx.x;
    const int row0 = blockIdx.x * 64;

    for (int i = tid; i < 128 * 64 / 4; i += 256)
        ((float4*)sW)[i] = ((const float4*)W)[i];
    for (int i = tid; i < 64 * 128 / 4; i += 256) {
        int r = i >> 5;
        int c4 = i & 31;
        int gr = row0 + r;
        float4 v = make_float4(0.f, 0.f, 0.f, 0.f);
        if (gr < NNODES) {
            float4 raw = *(const float4*)&g_agg1[(size_t)gr * 128 + c4 * 4];
            float4 sv = *(const float4*)&g_bns[c4 * 4];
            float4 tv = *(const float4*)&g_bnt[c4 * 4];
            v.x = fmaxf(raw.x * sv.x + tv.x, 0.f);
            v.y = fmaxf(raw.y * sv.y + tv.y, 0.f);
            v.z = fmaxf(raw.z * sv.z + tv.z, 0.f);
            v.w = fmaxf(raw.w * sv.w + tv.w, 0.f);
        }
        ((float4*)sA)[i] = v;
    }
    __syncthreads();

    const int tx = tid & 31, ty = tid >> 5;
    const int r0 = ty * 8, c0 = tx * 2;
    float acc[8][2];
#pragma unroll
    for (int i = 0; i < 8; i++) { acc[i][0] = 0.f; acc[i][1] = 0.f; }

    for (int k = 0; k < 128; k += 4) {
        float2 wv[4];
#pragma unroll
        for (int kk = 0; kk < 4; kk++)
            wv[kk] = *(const float2*)&sW[(k + kk) * 64 + c0];
#pragma unroll
        for (int i = 0; i < 8; i++) {
            float4 av = *(const float4*)&sA[(r0 + i) * 128 + k];
            acc[i][0] += av.x * wv[0].x + av.y * wv[1].x + av.z * wv[2].x + av.w * wv[3].x;
            acc[i][1] += av.x * wv[0].y + av.y * wv[1].y + av.z * wv[2].y + av.w * wv[3].y;
        }
    }

    float bx = b2[c0], by = b2[c0 + 1];
#pragma unroll
    for (int i = 0; i < 8; i++) {
        int gr = row0 + r0 + i;
        if (gr < NNODES) {
            float di = g_dinv[gr];
            float d2 = di * di;
            float2 h = make_float2(acc[i][0], acc[i][1]);
            *(float2*)&g_h2[(size_t)gr * 64 + c0] = h;
            float2 o = make_float2(h.x * d2 + bx, h.y * d2 + by);
            *(float2*)&out[(size_t)gr * 64 + c0] = o;
        }
    }
}

// ---------------- scatter layer 2: 2 edges per warp, 16 lanes x v4 RED each ----------------
__global__ void scatter2_kernel(const void* __restrict__ ei, int E, float* __restrict__ out) {
    int gw = (blockIdx.x * blockDim.x + threadIdx.x) >> 5;
    int lane = threadIdx.x & 31;
    int half = lane >> 4;          // 0 or 1
    int sub = lane & 15;
    long long e = (long long)gw * 2 + half;
    if (e >= E) return;
    unsigned mask = 0xFFFFu << (half * 16);
    int s = 0, d = 0;
    float norm = 0.f;
    if (sub == 0) {
        s = ld_idx(ei, e);
        d = ld_idx(ei, (long long)E + e);
        norm = g_dinv[s] * g_dinv[d];
    }
    s = __shfl_sync(mask, s, half * 16);
    d = __shfl_sync(mask, d, half * 16);
    norm = __shfl_sync(mask, norm, half * 16);

    float4 v = *(const float4*)&g_h2[(size_t)s * 64 + sub * 4];
    red_add_v4(&out[(size_t)d * 64 + sub * 4],
               make_float4(v.x * norm, v.y * norm, v.z * norm, v.w * norm));
}

// ---------------- launch ----------------
extern "C" void kernel_launch(void* const* d_in, const int* in_sizes, int n_in,
                              void* d_out, int out_size) {
    const float* x     = (const float*)d_in[0];
    const void*  ei    = d_in[1];
    const float* W1    = (const float*)d_in[2];
    const float* b1    = (const float*)d_in[3];
    const float* gamma = (const float*)d_in[4];
    const float* beta  = (const float*)d_in[5];
    const float* rmean = (const float*)d_in[6];
    const float* rvar  = (const float*)d_in[7];
    const float* W2    = (const float*)d_in[8];
    const float* b2    = (const float*)d_in[9];
    float* out = (float*)d_out;

    const int E = in_sizes[1] / 2;

    cudaFuncSetAttribute(gemm1_kernel, cudaFuncAttributeMaxDynamicSharedMemorySize, 96 * 1024);
    cudaFuncSetAttribute(gemm2_kernel, cudaFuncAttributeMaxDynamicSharedMemorySize, 64 * 1024);

    detect_idx_kernel<<<1, 1>>>(ei);

    int nblk = (NNODES + 255) / 256;
    deg_init_kernel<<<nblk, 256>>>();
    deg_count_kernel<<<(E + 255) / 256, 256>>>(ei, E);
    dinv_bn_kernel<<<nblk, 256>>>(b1, gamma, beta, rmean, rvar);

    int gblk = (NNODES + 63) / 64;
    gemm1_kernel<<<gblk, 256, 96 * 1024>>>(x, W1);

    // layer-1 scatter: 1 warp/edge
    {
        long long th = (long long)E * 32;
        scatter1_kernel<<<(int)((th + 255) / 256), 256>>>(ei, E);
    }

    gemm2_kernel<<<gblk, 256, 64 * 1024>>>(W2, b2, out);

    // layer-2 scatter: 2 edges/warp
    {
        long long warps = ((long long)E + 1) / 2;
        long long th = warps * 32;
        scatter2_kernel<<<(int)((th + 255) / 256), 256>>>(ei, E, out);
    }
}

// round 4
// speedup vs baseline: 1.4731x; 1.1078x over previous
#include <cuda_runtime.h>
#include <cuda_bf16.h>
#include <stdint.h>

#define NNODES 100000
#define H1DIM 128
#define H2DIM 64
#define BN_EPS 1e-5f
#define PAD 136   // bf16 elements per smem row (128 data + 8 pad) -> conflict-free frags

// ---------------- scratch ----------------
__device__ float g_deg[NNODES];
__device__ float g_dinv[NNODES];
__device__ float g_h1[(size_t)NNODES * H1DIM];
__device__ float g_agg1[(size_t)NNODES * H1DIM];
__device__ float g_h2[(size_t)NNODES * H2DIM];
__device__ float g_bns[H1DIM];
__device__ float g_bnt[H1DIM];
__device__ int   g_is64;

// ---------------- helpers ----------------
__device__ __forceinline__ void red_add_v4(float* p, float4 v) {
    asm volatile("red.global.add.v4.f32 [%0], {%1, %2, %3, %4};"
                 :: "l"(p), "f"(v.x), "f"(v.y), "f"(v.z), "f"(v.w) : "memory");
}
__device__ __forceinline__ void mma_bf16(float* c, const uint32_t* a, uint32_t b0, uint32_t b1) {
    asm volatile("mma.sync.aligned.m16n8k16.row.col.f32.bf16.bf16.f32 "
                 "{%0,%1,%2,%3}, {%4,%5,%6,%7}, {%8,%9}, {%0,%1,%2,%3};"
                 : "+f"(c[0]), "+f"(c[1]), "+f"(c[2]), "+f"(c[3])
                 : "r"(a[0]), "r"(a[1]), "r"(a[2]), "r"(a[3]), "r"(b0), "r"(b1));
}
__device__ __forceinline__ void split1(float v, __nv_bfloat16& hi, __nv_bfloat16& lo) {
    hi = __float2bfloat16_rn(v);
    lo = __float2bfloat16_rn(v - __bfloat162float(hi));
}
__device__ __forceinline__ void split2_packed(float a, float b, uint32_t& hi, uint32_t& lo) {
    __nv_bfloat16 ha, la, hb, lb;
    split1(a, ha, la);
    split1(b, hb, lb);
    hi = (uint32_t)__bfloat16_as_ushort(ha) | ((uint32_t)__bfloat16_as_ushort(hb) << 16);
    lo = (uint32_t)__bfloat16_as_ushort(la) | ((uint32_t)__bfloat16_as_ushort(lb) << 16);
}

// ---------------- edge index dtype detection ----------------
__global__ void detect_idx_kernel(const void* ei) {
    if (threadIdx.x == 0 && blockIdx.x == 0) {
        const long long* p = (const long long*)ei;
        int is64 = 1;
        for (int i = 0; i < 64; i++) {
            long long v = p[i];
            if (v < 0 || v >= (long long)NNODES) { is64 = 0; break; }
        }
        g_is64 = is64;
    }
}
__device__ __forceinline__ int ld_idx(const void* p, long long i) {
    if (g_is64) return (int)((const long long*)p)[i];
    return ((const int*)p)[i];
}

// ---------------- degree / dinv / BN ----------------
__global__ void deg_init_kernel() {
    int i = blockIdx.x * blockDim.x + threadIdx.x;
    if (i < NNODES) g_deg[i] = 1.0f;
}
__global__ void deg_count_kernel(const void* ei, int E) {
    int e = blockIdx.x * blockDim.x + threadIdx.x;
    if (e < E) atomicAdd(&g_deg[ld_idx(ei, (long long)E + e)], 1.0f);
}
__global__ void dinv_bn_kernel(const float* __restrict__ b1,
                               const float* __restrict__ gamma,
                               const float* __restrict__ beta,
                               const float* __restrict__ rmean,
                               const float* __restrict__ rvar) {
    int i = blockIdx.x * blockDim.x + threadIdx.x;
    if (i < NNODES) g_dinv[i] = rsqrtf(g_deg[i]);
    if (i < H1DIM) {
        float s = gamma[i] * rsqrtf(rvar[i] + BN_EPS);
        g_bns[i] = s;
        g_bnt[i] = (b1[i] - rmean[i]) * s + beta[i];
    }
}

// ---------------- GEMM1 (HMMA bf16 3-pass): h1 = x @ W1 ; agg1 = h1*dinv^2 ----------------
// Block: 128 rows x 128 cols, 256 threads = 8 warps in 4x2 grid, warp tile 32x64.
#define SM1_TOTAL (4 * 128 * PAD * 2)  // Ahi, Alo, Bhi, Blo (each 128 x PAD bf16)

__global__ void __launch_bounds__(256) mma_gemm1(const float* __restrict__ x,
                                                 const float* __restrict__ W) {
    extern __shared__ __nv_bfloat16 sm[];
    __nv_bfloat16* sAh = sm;
    __nv_bfloat16* sAl = sm + 128 * PAD;
    __nv_bfloat16* sBh = sm + 2 * 128 * PAD;
    __nv_bfloat16* sBl = sm + 3 * 128 * PAD;
    const int tid = threadIdx.x, wid = tid >> 5, lid = tid & 31;
    const int row0 = blockIdx.x * 128;

    // B = W1 transposed: Bt[n][k] = W[k][n]
    for (int i = tid; i < 128 * 128; i += 256) {
        int k = i >> 7, n = i & 127;
        __nv_bfloat16 hb, lb;
        split1(W[k * 128 + n], hb, lb);
        sBh[n * PAD + k] = hb;
        sBl[n * PAD + k] = lb;
    }
    // A = x tile (float2 per iter)
    for (int i = tid; i < 128 * 64; i += 256) {
        int r = i >> 6, c = i & 63;
        int gr = row0 + r;
        float2 v = make_float2(0.f, 0.f);
        if (gr < NNODES) v = ((const float2*)x)[(size_t)gr * 64 + c];
        uint32_t hi, lo;
        split2_packed(v.x, v.y, hi, lo);
        *(uint32_t*)&sAh[r * PAD + c * 2] = hi;
        *(uint32_t*)&sAl[r * PAD + c * 2] = lo;
    }
    __syncthreads();

    const int wr = wid >> 1, wc = wid & 1;
    const int g = lid >> 2, tg = lid & 3;
    const int ar0 = wr * 32, nc0 = wc * 64;

    float acc[2][8][4];
#pragma unroll
    for (int mi = 0; mi < 2; mi++)
#pragma unroll
        for (int ni = 0; ni < 8; ni++)
#pragma unroll
            for (int j = 0; j < 4; j++) acc[mi][ni][j] = 0.f;

#pragma unroll 1
    for (int pass = 0; pass < 3; pass++) {
        const __nv_bfloat16* A = (pass == 2) ? sAl : sAh;
        const __nv_bfloat16* B = (pass == 1) ? sBl : sBh;
#pragma unroll 1
        for (int ks = 0; ks < 8; ks++) {
            int k0 = ks * 16;
            uint32_t a[2][4];
#pragma unroll
            for (int mi = 0; mi < 2; mi++) {
                int r = ar0 + mi * 16;
                a[mi][0] = *(const uint32_t*)&A[(r + g) * PAD + k0 + tg * 2];
                a[mi][1] = *(const uint32_t*)&A[(r + g + 8) * PAD + k0 + tg * 2];
                a[mi][2] = *(const uint32_t*)&A[(r + g) * PAD + k0 + 8 + tg * 2];
                a[mi][3] = *(const uint32_t*)&A[(r + g + 8) * PAD + k0 + 8 + tg * 2];
            }
#pragma unroll
            for (int ni = 0; ni < 8; ni++) {
                int n = nc0 + ni * 8;
                uint32_t b0 = *(const uint32_t*)&B[(n + g) * PAD + k0 + tg * 2];
                uint32_t b1 = *(const uint32_t*)&B[(n + g) * PAD + k0 + 8 + tg * 2];
                mma_bf16(acc[0][ni], a[0], b0, b1);
                mma_bf16(acc[1][ni], a[1], b0, b1);
            }
        }
    }

    // epilogue: h1 = acc ; agg1 = acc * dinv^2
#pragma unroll
    for (int mi = 0; mi < 2; mi++) {
#pragma unroll
        for (int h = 0; h < 2; h++) {
            int r = row0 + ar0 + mi * 16 + g + h * 8;
            if (r < NNODES) {
                float di = g_dinv[r];
                float d2 = di * di;
#pragma unroll
                for (int ni = 0; ni < 8; ni++) {
                    int c = nc0 + ni * 8 + tg * 2;
                    float2 hv = make_float2(acc[mi][ni][h * 2], acc[mi][ni][h * 2 + 1]);
                    *(float2*)&g_h1[(size_t)r * 128 + c] = hv;
                    *(float2*)&g_agg1[(size_t)r * 128 + c] = make_float2(hv.x * d2, hv.y * d2);
                }
            }
        }
    }
}

// ---------------- scatter layer 1 ----------------
__global__ void scatter1_kernel(const void* __restrict__ ei, int E) {
    int gw = (blockIdx.x * blockDim.x + threadIdx.x) >> 5;
    int lane = threadIdx.x & 31;
    if (gw >= E) return;
    int s = 0, d = 0;
    float norm = 0.f;
    if (lane == 0) {
        s = ld_idx(ei, gw);
        d = ld_idx(ei, (long long)E + gw);
        norm = g_dinv[s] * g_dinv[d];
    }
    s = __shfl_sync(0xFFFFFFFFu, s, 0);
    d = __shfl_sync(0xFFFFFFFFu, d, 0);
    norm = __shfl_sync(0xFFFFFFFFu, norm, 0);
    float4 v = *(const float4*)&g_h1[(size_t)s * 128 + lane * 4];
    red_add_v4(&g_agg1[(size_t)d * 128 + lane * 4],
               make_float4(v.x * norm, v.y * norm, v.z * norm, v.w * norm));
}

// ---------------- GEMM2 (HMMA bf16 3-pass): h2 = bnrelu(agg1) @ W2 ; out = h2*dinv^2 + b2 ----
// Block: 128 rows x 64 cols, 8 warps in 4x2 grid, warp tile 32x32.
#define SM2_TOTAL (2 * 128 * PAD * 2 + 2 * 64 * PAD * 2)

__global__ void __launch_bounds__(256) mma_gemm2(const float* __restrict__ W,
                                                 const float* __restrict__ b2,
                                                 float* __restrict__ out) {
    extern __shared__ __nv_bfloat16 sm[];
    __nv_bfloat16* sAh = sm;
    __nv_bfloat16* sAl = sm + 128 * PAD;
    __nv_bfloat16* sBh = sm + 2 * 128 * PAD;
    __nv_bfloat16* sBl = sm + 2 * 128 * PAD + 64 * PAD;
    const int tid = threadIdx.x, wid = tid >> 5, lid = tid & 31;
    const int row0 = blockIdx.x * 128;

    // B = W2 transposed: Bt[n][k] = W2[k][n], n<64 k<128
    for (int i = tid; i < 128 * 64; i += 256) {
        int k = i >> 6, n = i & 63;
        __nv_bfloat16 hb, lb;
        split1(W[k * 64 + n], hb, lb);
        sBh[n * PAD + k] = hb;
        sBl[n * PAD + k] = lb;
    }
    // A = bnrelu(agg1) tile
    for (int i = tid; i < 128 * 64; i += 256) {
        int r = i >> 6, c = i & 63;
        int gr = row0 + r;
        float2 v = make_float2(0.f, 0.f);
        if (gr < NNODES) {
            float2 raw = *(const float2*)&g_agg1[(size_t)gr * 128 + c * 2];
            float2 s2 = *(const float2*)&g_bns[c * 2];
            float2 t2 = *(const float2*)&g_bnt[c * 2];
            v.x = fmaxf(raw.x * s2.x + t2.x, 0.f);
            v.y = fmaxf(raw.y * s2.y + t2.y, 0.f);
        }
        uint32_t hi, lo;
        split2_packed(v.x, v.y, hi, lo);
        *(uint32_t*)&sAh[r * PAD + c * 2] = hi;
        *(uint32_t*)&sAl[r * PAD + c * 2] = lo;
    }
    __syncthreads();

    const int wr = wid >> 1, wc = wid & 1;
    const int g = lid >> 2, tg = lid & 3;
    const int ar0 = wr * 32, nc0 = wc * 32;

    float acc[2][4][4];
#pragma unroll
    for (int mi = 0; mi < 2; mi++)
#pragma unroll
        for (int ni = 0; ni < 4; ni++)
#pragma unroll
            for (int j = 0; j < 4; j++) acc[mi][ni][j] = 0.f;

#pragma unroll 1
    for (int pass = 0; pass < 3; pass++) {
        const __nv_bfloat16* A = (pass == 2) ? sAl : sAh;
        const __nv_bfloat16* B = (pass == 1) ? sBl : sBh;
#pragma unroll 1
        for (int ks = 0; ks < 8; ks++) {
            int k0 = ks * 16;
            uint32_t a[2][4];
#pragma unroll
            for (int mi = 0; mi < 2; mi++) {
                int r = ar0 + mi * 16;
                a[mi][0] = *(const uint32_t*)&A[(r + g) * PAD + k0 + tg * 2];
                a[mi][1] = *(const uint32_t*)&A[(r + g + 8) * PAD + k0 + tg * 2];
                a[mi][2] = *(const uint32_t*)&A[(r + g) * PAD + k0 + 8 + tg * 2];
                a[mi][3] = *(const uint32_t*)&A[(r + g + 8) * PAD + k0 + 8 + tg * 2];
            }
#pragma unroll
            for (int ni = 0; ni < 4; ni++) {
                int n = nc0 + ni * 8;
                uint32_t b0 = *(const uint32_t*)&B[(n + g) * PAD + k0 + tg * 2];
                uint32_t b1 = *(const uint32_t*)&B[(n + g) * PAD + k0 + 8 + tg * 2];
                mma_bf16(acc[0][ni], a[0], b0, b1);
                mma_bf16(acc[1][ni], a[1], b0, b1);
            }
        }
    }

#pragma unroll
    for (int mi = 0; mi < 2; mi++) {
#pragma unroll
        for (int h = 0; h < 2; h++) {
            int r = row0 + ar0 + mi * 16 + g + h * 8;
            if (r < NNODES) {
                float di = g_dinv[r];
                float d2 = di * di;
#pragma unroll
                for (int ni = 0; ni < 4; ni++) {
                    int c = nc0 + ni * 8 + tg * 2;
                    float2 hv = make_float2(acc[mi][ni][h * 2], acc[mi][ni][h * 2 + 1]);
                    *(float2*)&g_h2[(size_t)r * 64 + c] = hv;
                    float2 bv = *(const float2*)&b2[c];
                    *(float2*)&out[(size_t)r * 64 + c] =
                        make_float2(hv.x * d2 + bv.x, hv.y * d2 + bv.y);
                }
            }
        }
    }
}

// ---------------- scatter layer 2 ----------------
__global__ void scatter2_kernel(const void* __restrict__ ei, int E, float* __restrict__ out) {
    int gw = (blockIdx.x * blockDim.x + threadIdx.x) >> 5;
    int lane = threadIdx.x & 31;
    int half = lane >> 4, sub = lane & 15;
    long long e = (long long)gw * 2 + half;
    if (e >= E) return;
    unsigned mask = 0xFFFFu << (half * 16);
    int s = 0, d = 0;
    float norm = 0.f;
    if (sub == 0) {
        s = ld_idx(ei, e);
        d = ld_idx(ei, (long long)E + e);
        norm = g_dinv[s] * g_dinv[d];
    }
    s = __shfl_sync(mask, s, half * 16);
    d = __shfl_sync(mask, d, half * 16);
    norm = __shfl_sync(mask, norm, half * 16);
    float4 v = *(const float4*)&g_h2[(size_t)s * 64 + sub * 4];
    red_add_v4(&out[(size_t)d * 64 + sub * 4],
               make_float4(v.x * norm, v.y * norm, v.z * norm, v.w * norm));
}

// ---------------- launch ----------------
extern "C" void kernel_launch(void* const* d_in, const int* in_sizes, int n_in,
                              void* d_out, int out_size) {
    const float* x     = (const float*)d_in[0];
    const void*  ei    = d_in[1];
    const float* W1    = (const float*)d_in[2];
    const float* b1    = (const float*)d_in[3];
    const float* gamma = (const float*)d_in[4];
    const float* beta  = (const float*)d_in[5];
    const float* rmean = (const float*)d_in[6];
    const float* rvar  = (const float*)d_in[7];
    const float* W2    = (const float*)d_in[8];
    const float* b2    = (const float*)d_in[9];
    float* out = (float*)d_out;

    const int E = in_sizes[1] / 2;

    cudaFuncSetAttribute(mma_gemm1, cudaFuncAttributeMaxDynamicSharedMemorySize, SM1_TOTAL);
    cudaFuncSetAttribute(mma_gemm2, cudaFuncAttributeMaxDynamicSharedMemorySize, SM2_TOTAL);

    detect_idx_kernel<<<1, 1>>>(ei);

    int nblk = (NNODES + 255) / 256;
    deg_init_kernel<<<nblk, 256>>>();
    deg_count_kernel<<<(E + 255) / 256, 256>>>(ei, E);
    dinv_bn_kernel<<<nblk, 256>>>(b1, gamma, beta, rmean, rvar);

    int gblk = (NNODES + 127) / 128;  // 782
    mma_gemm1<<<gblk, 256, SM1_TOTAL>>>(x, W1);

    {
        long long th = (long long)E * 32;
        scatter1_kernel<<<(int)((th + 255) / 256), 256>>>(ei, E);
    }

    mma_gemm2<<<gblk, 256, SM2_TOTAL>>>(W2, b2, out);

    {
        long long warps = ((long long)E + 1) / 2;
        long long th = warps * 32;
        scatter2_kernel<<<(int)((th + 255) / 256), 256>>>(ei, E, out);
    }
}

// round 5
// speedup vs baseline: 1.9357x; 1.3140x over previous
#include <cuda_runtime.h>
#include <cuda_bf16.h>
#include <stdint.h>

#define NNODES 100000
#define H1DIM 128
#define H2DIM 64
#define BN_EPS 1e-5f
#define PAD 136
#define EMAX (1 << 20)

// ---------------- scratch ----------------
__device__ int   g_degi[NNODES];
__device__ float g_dinv[NNODES];
__device__ int   g_rowptr[NNODES + 1];
__device__ int   g_cursor[NNODES];
__device__ int   g_blksum[512];
__device__ int   g_blkoff[512];
__device__ int   g_esrc[EMAX];
__device__ float g_enorm[EMAX];
__device__ float g_h1[(size_t)NNODES * H1DIM];
__device__ float g_agg1[(size_t)NNODES * H1DIM];
__device__ float g_h2[(size_t)NNODES * H2DIM];
__device__ float g_bns[H1DIM];
__device__ float g_bnt[H1DIM];
__device__ int   g_is64;

// ---------------- helpers ----------------
__device__ __forceinline__ void mma_bf16(float* c, const uint32_t* a, uint32_t b0, uint32_t b1) {
    asm volatile("mma.sync.aligned.m16n8k16.row.col.f32.bf16.bf16.f32 "
                 "{%0,%1,%2,%3}, {%4,%5,%6,%7}, {%8,%9}, {%0,%1,%2,%3};"
                 : "+f"(c[0]), "+f"(c[1]), "+f"(c[2]), "+f"(c[3])
                 : "r"(a[0]), "r"(a[1]), "r"(a[2]), "r"(a[3]), "r"(b0), "r"(b1));
}
__device__ __forceinline__ void split1(float v, __nv_bfloat16& hi, __nv_bfloat16& lo) {
    hi = __float2bfloat16_rn(v);
    lo = __float2bfloat16_rn(v - __bfloat162float(hi));
}
__device__ __forceinline__ void split2_packed(float a, float b, uint32_t& hi, uint32_t& lo) {
    __nv_bfloat16 ha, la, hb, lb;
    split1(a, ha, la);
    split1(b, hb, lb);
    hi = (uint32_t)__bfloat16_as_ushort(ha) | ((uint32_t)__bfloat16_as_ushort(hb) << 16);
    lo = (uint32_t)__bfloat16_as_ushort(la) | ((uint32_t)__bfloat16_as_ushort(lb) << 16);
}

// ---------------- edge index dtype detection ----------------
__global__ void detect_idx_kernel(const void* ei) {
    if (threadIdx.x == 0 && blockIdx.x == 0) {
        const long long* p = (const long long*)ei;
        int is64 = 1;
        for (int i = 0; i < 64; i++) {
            long long v = p[i];
            if (v < 0 || v >= (long long)NNODES) { is64 = 0; break; }
        }
        g_is64 = is64;
    }
}
__device__ __forceinline__ int ld_idx(const void* p, long long i) {
    if (g_is64) return (int)((const long long*)p)[i];
    return ((const int*)p)[i];
}

// ---------------- degree / dinv / BN ----------------
__global__ void deg_init_kernel() {
    int i = blockIdx.x * blockDim.x + threadIdx.x;
    if (i < NNODES) g_degi[i] = 0;
}
__global__ void deg_count_kernel(const void* ei, int E) {
    int e = blockIdx.x * blockDim.x + threadIdx.x;
    if (e < E) atomicAdd(&g_degi[ld_idx(ei, (long long)E + e)], 1);
}
__global__ void dinv_bn_kernel(const float* __restrict__ b1,
                               const float* __restrict__ gamma,
                               const float* __restrict__ beta,
                               const float* __restrict__ rmean,
                               const float* __restrict__ rvar) {
    int i = blockIdx.x * blockDim.x + threadIdx.x;
    if (i < NNODES) g_dinv[i] = rsqrtf((float)g_degi[i] + 1.0f);
    if (i < H1DIM) {
        float s = gamma[i] * rsqrtf(rvar[i] + BN_EPS);
        g_bns[i] = s;
        g_bnt[i] = (b1[i] - rmean[i]) * s + beta[i];
    }
}

// ---------------- exclusive scan (3 kernels) ----------------
__global__ void scan1_kernel() {
    __shared__ int sm[256];
    int i = blockIdx.x * 256 + threadIdx.x;
    int v = (i < NNODES) ? g_degi[i] : 0;
    sm[threadIdx.x] = v;
    __syncthreads();
    for (int off = 1; off < 256; off <<= 1) {
        int t = (threadIdx.x >= off) ? sm[threadIdx.x - off] : 0;
        __syncthreads();
        sm[threadIdx.x] += t;
        __syncthreads();
    }
    if (i < NNODES) g_rowptr[i] = sm[threadIdx.x] - v;
    if (threadIdx.x == 255) g_blksum[blockIdx.x] = sm[255];
}
__global__ void scan2_kernel(int nb) {
    __shared__ int sm[512];
    int v = (threadIdx.x < nb) ? g_blksum[threadIdx.x] : 0;
    sm[threadIdx.x] = v;
    __syncthreads();
    for (int off = 1; off < 512; off <<= 1) {
        int t = (threadIdx.x >= off) ? sm[threadIdx.x - off] : 0;
        __syncthreads();
        sm[threadIdx.x] += t;
        __syncthreads();
    }
    if (threadIdx.x < nb) g_blkoff[threadIdx.x] = sm[threadIdx.x] - v;
}
__global__ void scan3_kernel(int E) {
    int i = blockIdx.x * blockDim.x + threadIdx.x;
    if (i < NNODES) {
        int r = g_rowptr[i] + g_blkoff[i >> 8];
        g_rowptr[i] = r;
        g_cursor[i] = r;
    }
    if (i == 0) g_rowptr[NNODES] = E;
}

// ---------------- permute edges into CSR ----------------
__global__ void permute_kernel(const void* __restrict__ ei, int E) {
    int e = blockIdx.x * blockDim.x + threadIdx.x;
    if (e >= E) return;
    int s = ld_idx(ei, e);
    int d = ld_idx(ei, (long long)E + e);
    float nm = g_dinv[s] * g_dinv[d];
    int pos = atomicAdd(&g_cursor[d], 1);
    g_esrc[pos] = s;
    g_enorm[pos] = nm;
}

// ---------------- GEMM1 (HMMA bf16 3-pass): h1 = x @ W1 ----------------
#define SM1_TOTAL (4 * 128 * PAD * 2)
__global__ void __launch_bounds__(256) mma_gemm1(const float* __restrict__ x,
                                                 const float* __restrict__ W) {
    extern __shared__ __nv_bfloat16 sm[];
    __nv_bfloat16* sAh = sm;
    __nv_bfloat16* sAl = sm + 128 * PAD;
    __nv_bfloat16* sBh = sm + 2 * 128 * PAD;
    __nv_bfloat16* sBl = sm + 3 * 128 * PAD;
    const int tid = threadIdx.x, wid = tid >> 5, lid = tid & 31;
    const int row0 = blockIdx.x * 128;

    for (int i = tid; i < 128 * 128; i += 256) {
        int k = i >> 7, n = i & 127;
        __nv_bfloat16 hb, lb;
        split1(W[k * 128 + n], hb, lb);
        sBh[n * PAD + k] = hb;
        sBl[n * PAD + k] = lb;
    }
    for (int i = tid; i < 128 * 64; i += 256) {
        int r = i >> 6, c = i & 63;
        int gr = row0 + r;
        float2 v = make_float2(0.f, 0.f);
        if (gr < NNODES) v = ((const float2*)x)[(size_t)gr * 64 + c];
        uint32_t hi, lo;
        split2_packed(v.x, v.y, hi, lo);
        *(uint32_t*)&sAh[r * PAD + c * 2] = hi;
        *(uint32_t*)&sAl[r * PAD + c * 2] = lo;
    }
    __syncthreads();

    const int wr = wid >> 1, wc = wid & 1;
    const int g = lid >> 2, tg = lid & 3;
    const int ar0 = wr * 32, nc0 = wc * 64;

    float acc[2][8][4];
#pragma unroll
    for (int mi = 0; mi < 2; mi++)
#pragma unroll
        for (int ni = 0; ni < 8; ni++)
#pragma unroll
            for (int j = 0; j < 4; j++) acc[mi][ni][j] = 0.f;

#pragma unroll 1
    for (int pass = 0; pass < 3; pass++) {
        const __nv_bfloat16* A = (pass == 2) ? sAl : sAh;
        const __nv_bfloat16* B = (pass == 1) ? sBl : sBh;
#pragma unroll 1
        for (int ks = 0; ks < 8; ks++) {
            int k0 = ks * 16;
            uint32_t a[2][4];
#pragma unroll
            for (int mi = 0; mi < 2; mi++) {
                int r = ar0 + mi * 16;
                a[mi][0] = *(const uint32_t*)&A[(r + g) * PAD + k0 + tg * 2];
                a[mi][1] = *(const uint32_t*)&A[(r + g + 8) * PAD + k0 + tg * 2];
                a[mi][2] = *(const uint32_t*)&A[(r + g) * PAD + k0 + 8 + tg * 2];
                a[mi][3] = *(const uint32_t*)&A[(r + g + 8) * PAD + k0 + 8 + tg * 2];
            }
#pragma unroll
            for (int ni = 0; ni < 8; ni++) {
                int n = nc0 + ni * 8;
                uint32_t b0 = *(const uint32_t*)&B[(n + g) * PAD + k0 + tg * 2];
                uint32_t b1 = *(const uint32_t*)&B[(n + g) * PAD + k0 + 8 + tg * 2];
                mma_bf16(acc[0][ni], a[0], b0, b1);
                mma_bf16(acc[1][ni], a[1], b0, b1);
            }
        }
    }

#pragma unroll
    for (int mi = 0; mi < 2; mi++)
#pragma unroll
        for (int h = 0; h < 2; h++) {
            int r = row0 + ar0 + mi * 16 + g + h * 8;
            if (r < NNODES) {
#pragma unroll
                for (int ni = 0; ni < 8; ni++) {
                    int c = nc0 + ni * 8 + tg * 2;
                    *(float2*)&g_h1[(size_t)r * 128 + c] =
                        make_float2(acc[mi][ni][h * 2], acc[mi][ni][h * 2 + 1]);
                }
            }
        }
}

// ---------------- agg1: warp per node, gather-reduce over in-edges ----------------
__global__ void __launch_bounds__(256) agg1_kernel() {
    int w = (blockIdx.x * blockDim.x + threadIdx.x) >> 5;
    int lane = threadIdx.x & 31;
    if (w >= NNODES) return;
    int beg = g_rowptr[w], end = g_rowptr[w + 1];
    float di = g_dinv[w];
    float d2 = di * di;
    const float4* h1 = (const float4*)g_h1;
    float4 acc = h1[(size_t)w * 32 + lane];
    acc.x *= d2; acc.y *= d2; acc.z *= d2; acc.w *= d2;
    int j = beg;
    for (; j + 2 <= end; j += 2) {
        int s0 = g_esrc[j], s1 = g_esrc[j + 1];
        float n0 = g_enorm[j], n1 = g_enorm[j + 1];
        float4 v0 = h1[(size_t)s0 * 32 + lane];
        float4 v1 = h1[(size_t)s1 * 32 + lane];
        acc.x += v0.x * n0 + v1.x * n1;
        acc.y += v0.y * n0 + v1.y * n1;
        acc.z += v0.z * n0 + v1.z * n1;
        acc.w += v0.w * n0 + v1.w * n1;
    }
    if (j < end) {
        int s0 = g_esrc[j];
        float n0 = g_enorm[j];
        float4 v0 = h1[(size_t)s0 * 32 + lane];
        acc.x += v0.x * n0; acc.y += v0.y * n0; acc.z += v0.z * n0; acc.w += v0.w * n0;
    }
    ((float4*)g_agg1)[(size_t)w * 32 + lane] = acc;
}

// ---------------- GEMM2 (HMMA bf16 3-pass): h2 = bnrelu(agg1) @ W2 ----------------
#define SM2_TOTAL (2 * 128 * PAD * 2 + 2 * 64 * PAD * 2)
__global__ void __launch_bounds__(256) mma_gemm2(const float* __restrict__ W) {
    extern __shared__ __nv_bfloat16 sm[];
    __nv_bfloat16* sAh = sm;
    __nv_bfloat16* sAl = sm + 128 * PAD;
    __nv_bfloat16* sBh = sm + 2 * 128 * PAD;
    __nv_bfloat16* sBl = sm + 2 * 128 * PAD + 64 * PAD;
    const int tid = threadIdx.x, wid = tid >> 5, lid = tid & 31;
    const int row0 = blockIdx.x * 128;

    for (int i = tid; i < 128 * 64; i += 256) {
        int k = i >> 6, n = i & 63;
        __nv_bfloat16 hb, lb;
        split1(W[k * 64 + n], hb, lb);
        sBh[n * PAD + k] = hb;
        sBl[n * PAD + k] = lb;
    }
    for (int i = tid; i < 128 * 64; i += 256) {
        int r = i >> 6, c = i & 63;
        int gr = row0 + r;
        float2 v = make_float2(0.f, 0.f);
        if (gr < NNODES) {
            float2 raw = *(const float2*)&g_agg1[(size_t)gr * 128 + c * 2];
            float2 s2 = *(const float2*)&g_bns[c * 2];
            float2 t2 = *(const float2*)&g_bnt[c * 2];
            v.x = fmaxf(raw.x * s2.x + t2.x, 0.f);
            v.y = fmaxf(raw.y * s2.y + t2.y, 0.f);
        }
        uint32_t hi, lo;
        split2_packed(v.x, v.y, hi, lo);
        *(uint32_t*)&sAh[r * PAD + c * 2] = hi;
        *(uint32_t*)&sAl[r * PAD + c * 2] = lo;
    }
    __syncthreads();

    const int wr = wid >> 1, wc = wid & 1;
    const int g = lid >> 2, tg = lid & 3;
    const int ar0 = wr * 32, nc0 = wc * 32;

    float acc[2][4][4];
#pragma unroll
    for (int mi = 0; mi < 2; mi++)
#pragma unroll
        for (int ni = 0; ni < 4; ni++)
#pragma unroll
            for (int j = 0; j < 4; j++) acc[mi][ni][j] = 0.f;

#pragma unroll 1
    for (int pass = 0; pass < 3; pass++) {
        const __nv_bfloat16* A = (pass == 2) ? sAl : sAh;
        const __nv_bfloat16* B = (pass == 1) ? sBl : sBh;
#pragma unroll 1
        for (int ks = 0; ks < 8; ks++) {
            int k0 = ks * 16;
            uint32_t a[2][4];
#pragma unroll
            for (int mi = 0; mi < 2; mi++) {
                int r = ar0 + mi * 16;
                a[mi][0] = *(const uint32_t*)&A[(r + g) * PAD + k0 + tg * 2];
                a[mi][1] = *(const uint32_t*)&A[(r + g + 8) * PAD + k0 + tg * 2];
                a[mi][2] = *(const uint32_t*)&A[(r + g) * PAD + k0 + 8 + tg * 2];
                a[mi][3] = *(const uint32_t*)&A[(r + g + 8) * PAD + k0 + 8 + tg * 2];
            }
#pragma unroll
            for (int ni = 0; ni < 4; ni++) {
                int n = nc0 + ni * 8;
                uint32_t b0 = *(const uint32_t*)&B[(n + g) * PAD + k0 + tg * 2];
                uint32_t b1 = *(const uint32_t*)&B[(n + g) * PAD + k0 + 8 + tg * 2];
                mma_bf16(acc[0][ni], a[0], b0, b1);
                mma_bf16(acc[1][ni], a[1], b0, b1);
            }
        }
    }

#pragma unroll
    for (int mi = 0; mi < 2; mi++)
#pragma unroll
        for (int h = 0; h < 2; h++) {
            int r = row0 + ar0 + mi * 16 + g + h * 8;
            if (r < NNODES) {
#pragma unroll
                for (int ni = 0; ni < 4; ni++) {
                    int c = nc0 + ni * 8 + tg * 2;
                    *(float2*)&g_h2[(size_t)r * 64 + c] =
                        make_float2(acc[mi][ni][h * 2], acc[mi][ni][h * 2 + 1]);
                }
            }
        }
}

// ---------------- agg2: half-warp per node ----------------
__global__ void __launch_bounds__(256) agg2_kernel(const float* __restrict__ b2,
                                                   float* __restrict__ out) {
    int t = blockIdx.x * blockDim.x + threadIdx.x;
    int hw = t >> 4;
    int sub = t & 15;
    if (hw >= NNODES) return;
    int beg = g_rowptr[hw], end = g_rowptr[hw + 1];
    float di = g_dinv[hw];
    float d2 = di * di;
    const float4* h2 = (const float4*)g_h2;
    float4 acc = h2[(size_t)hw * 16 + sub];
    acc.x *= d2; acc.y *= d2; acc.z *= d2; acc.w *= d2;
    int j = beg;
    for (; j + 2 <= end; j += 2) {
        int s0 = g_esrc[j], s1 = g_esrc[j + 1];
        float n0 = g_enorm[j], n1 = g_enorm[j + 1];
        float4 v0 = h2[(size_t)s0 * 16 + sub];
        float4 v1 = h2[(size_t)s1 * 16 + sub];
        acc.x += v0.x * n0 + v1.x * n1;
        acc.y += v0.y * n0 + v1.y * n1;
        acc.z += v0.z * n0 + v1.z * n1;
        acc.w += v0.w * n0 + v1.w * n1;
    }
    if (j < end) {
        int s0 = g_esrc[j];
        float n0 = g_enorm[j];
        float4 v0 = h2[(size_t)s0 * 16 + sub];
        acc.x += v0.x * n0; acc.y += v0.y * n0; acc.z += v0.z * n0; acc.w += v0.w * n0;
    }
    float4 bv = ((const float4*)b2)[sub];
    ((float4*)out)[(size_t)hw * 16 + sub] =
        make_float4(acc.x + bv.x, acc.y + bv.y, acc.z + bv.z, acc.w + bv.w);
}

// ---------------- launch ----------------
extern "C" void kernel_launch(void* const* d_in, const int* in_sizes, int n_in,
                              void* d_out, int out_size) {
    const float* x     = (const float*)d_in[0];
    const void*  ei    = d_in[1];
    const float* W1    = (const float*)d_in[2];
    const float* b1    = (const float*)d_in[3];
    const float* gamma = (const float*)d_in[4];
    const float* beta  = (const float*)d_in[5];
    const float* rmean = (const float*)d_in[6];
    const float* rvar  = (const float*)d_in[7];
    const float* W2    = (const float*)d_in[8];
    const float* b2    = (const float*)d_in[9];
    float* out = (float*)d_out;

    const int E = in_sizes[1] / 2;

    cudaFuncSetAttribute(mma_gemm1, cudaFuncAttributeMaxDynamicSharedMemorySize, SM1_TOTAL);
    cudaFuncSetAttribute(mma_gemm2, cudaFuncAttributeMaxDynamicSharedMemorySize, SM2_TOTAL);

    detect_idx_kernel<<<1, 1>>>(ei);

    int nblk = (NNODES + 255) / 256;  // 391
    deg_init_kernel<<<nblk, 256>>>();
    deg_count_kernel<<<(E + 255) / 256, 256>>>(ei, E);
    dinv_bn_kernel<<<nblk, 256>>>(b1, gamma, beta, rmean, rvar);

    // CSR build
    scan1_kernel<<<nblk, 256>>>();
    scan2_kernel<<<1, 512>>>(nblk);
    scan3_kernel<<<nblk, 256>>>(E);
    permute_kernel<<<(E + 255) / 256, 256>>>(ei, E);

    int gblk = (NNODES + 127) / 128;  // 782
    mma_gemm1<<<gblk, 256, SM1_TOTAL>>>(x, W1);

    // agg1: 1 warp/node
    {
        long long th = (long long)NNODES * 32;
        agg1_kernel<<<(int)((th + 255) / 256), 256>>>();
    }

    mma_gemm2<<<gblk, 256, SM2_TOTAL>>>(W2);

    // agg2: 1 half-warp/node
    {
        long long th = (long long)NNODES * 16;
        agg2_kernel<<<(int)((th + 255) / 256), 256>>>(b2, out);
    }
}

// round 6
// speedup vs baseline: 2.2986x; 1.1875x over previous
#include <cuda_runtime.h>
#include <cuda_bf16.h>
#include <stdint.h>

#define NNODES 100000
#define H1DIM 128
#define H2DIM 64
#define BN_EPS 1e-5f
#define PAD 136
#define EMAX (1 << 20)

// ---------------- scratch ----------------
__device__ int   g_degi[NNODES];
__device__ float g_dinv[NNODES];
__device__ int   g_rowptr[NNODES + 1];
__device__ int   g_cursor[NNODES];
__device__ int   g_blksum[512];
__device__ int   g_blkoff[512];
__device__ int   g_esrc[EMAX];
__device__ float g_enorm[EMAX];
__device__ float g_h1[(size_t)NNODES * H1DIM];
__device__ uint32_t g_a2h[(size_t)NNODES * 64];   // bnrelu(agg1) hi bf16x2
__device__ uint32_t g_a2l[(size_t)NNODES * 64];   // bnrelu(agg1) lo bf16x2
__device__ float g_h2[(size_t)NNODES * H2DIM];
__device__ float g_bns[H1DIM];
__device__ float g_bnt[H1DIM];
__device__ __align__(16) __nv_bfloat16 g_w1h[128 * 128];  // W1^T hi  [n][k]
__device__ __align__(16) __nv_bfloat16 g_w1l[128 * 128];
__device__ __align__(16) __nv_bfloat16 g_w2h[64 * 128];   // W2^T hi
__device__ __align__(16) __nv_bfloat16 g_w2l[64 * 128];
__device__ int   g_is64;

// ---------------- helpers ----------------
__device__ __forceinline__ void mma_bf16(float* c, const uint32_t* a, uint32_t b0, uint32_t b1) {
    asm volatile("mma.sync.aligned.m16n8k16.row.col.f32.bf16.bf16.f32 "
                 "{%0,%1,%2,%3}, {%4,%5,%6,%7}, {%8,%9}, {%0,%1,%2,%3};"
                 : "+f"(c[0]), "+f"(c[1]), "+f"(c[2]), "+f"(c[3])
                 : "r"(a[0]), "r"(a[1]), "r"(a[2]), "r"(a[3]), "r"(b0), "r"(b1));
}
__device__ __forceinline__ void ldsm_x4(uint32_t& r0, uint32_t& r1, uint32_t& r2, uint32_t& r3,
                                        uint32_t addr) {
    asm volatile("ldmatrix.sync.aligned.m8n8.x4.shared.b16 {%0,%1,%2,%3}, [%4];"
                 : "=r"(r0), "=r"(r1), "=r"(r2), "=r"(r3) : "r"(addr));
}
__device__ __forceinline__ void split1(float v, __nv_bfloat16& hi, __nv_bfloat16& lo) {
    hi = __float2bfloat16_rn(v);
    lo = __float2bfloat16_rn(v - __bfloat162float(hi));
}
__device__ __forceinline__ void split2_packed(float a, float b, uint32_t& hi, uint32_t& lo) {
    __nv_bfloat16 ha, la, hb, lb;
    split1(a, ha, la);
    split1(b, hb, lb);
    hi = (uint32_t)__bfloat16_as_ushort(ha) | ((uint32_t)__bfloat16_as_ushort(hb) << 16);
    lo = (uint32_t)__bfloat16_as_ushort(la) | ((uint32_t)__bfloat16_as_ushort(lb) << 16);
}

// ---------------- init: zero degrees + detect edge dtype ----------------
__global__ void init_kernel(const void* ei) {
    int i = blockIdx.x * blockDim.x + threadIdx.x;
    if (i < NNODES) g_degi[i] = 0;
    if (i == 0) {
        const long long* p = (const long long*)ei;
        int is64 = 1;
        for (int j = 0; j < 64; j++) {
            long long v = p[j];
            if (v < 0 || v >= (long long)NNODES) { is64 = 0; break; }
        }
        g_is64 = is64;
    }
}
__device__ __forceinline__ int ld_idx(const void* p, long long i) {
    if (g_is64) return (int)((const long long*)p)[i];
    return ((const int*)p)[i];
}

// ---------------- W split (once) ----------------
__global__ void wsplit_kernel(const float* __restrict__ W1, const float* __restrict__ W2) {
    int i = blockIdx.x * blockDim.x + threadIdx.x;
    if (i < 128 * 128) {
        int k = i >> 7, n = i & 127;
        __nv_bfloat16 hb, lb;
        split1(W1[k * 128 + n], hb, lb);
        g_w1h[n * 128 + k] = hb;
        g_w1l[n * 128 + k] = lb;
    }
    if (i < 128 * 64) {
        int k = i >> 6, n = i & 63;
        __nv_bfloat16 hb, lb;
        split1(W2[k * 64 + n], hb, lb);
        g_w2h[n * 128 + k] = hb;
        g_w2l[n * 128 + k] = lb;
    }
}

// ---------------- degree / dinv / BN ----------------
__global__ void deg_count_kernel(const void* ei, int E) {
    int e = blockIdx.x * blockDim.x + threadIdx.x;
    if (e < E) atomicAdd(&g_degi[ld_idx(ei, (long long)E + e)], 1);
}
__global__ void dinv_bn_kernel(const float* __restrict__ b1,
                               const float* __restrict__ gamma,
                               const float* __restrict__ beta,
                               const float* __restrict__ rmean,
                               const float* __restrict__ rvar) {
    int i = blockIdx.x * blockDim.x + threadIdx.x;
    if (i < NNODES) g_dinv[i] = rsqrtf((float)g_degi[i] + 1.0f);
    if (i < H1DIM) {
        float s = gamma[i] * rsqrtf(rvar[i] + BN_EPS);
        g_bns[i] = s;
        g_bnt[i] = (b1[i] - rmean[i]) * s + beta[i];
    }
}

// ---------------- exclusive scan (3 kernels) ----------------
__global__ void scan1_kernel() {
    __shared__ int sm[256];
    int i = blockIdx.x * 256 + threadIdx.x;
    int v = (i < NNODES) ? g_degi[i] : 0;
    sm[threadIdx.x] = v;
    __syncthreads();
    for (int off = 1; off < 256; off <<= 1) {
        int t = (threadIdx.x >= off) ? sm[threadIdx.x - off] : 0;
        __syncthreads();
        sm[threadIdx.x] += t;
        __syncthreads();
    }
    if (i < NNODES) g_rowptr[i] = sm[threadIdx.x] - v;
    if (threadIdx.x == 255) g_blksum[blockIdx.x] = sm[255];
}
__global__ void scan2_kernel(int nb) {
    __shared__ int sm[512];
    int v = (threadIdx.x < nb) ? g_blksum[threadIdx.x] : 0;
    sm[threadIdx.x] = v;
    __syncthreads();
    for (int off = 1; off < 512; off <<= 1) {
        int t = (threadIdx.x >= off) ? sm[threadIdx.x - off] : 0;
        __syncthreads();
        sm[threadIdx.x] += t;
        __syncthreads();
    }
    if (threadIdx.x < nb) g_blkoff[threadIdx.x] = sm[threadIdx.x] - v;
}
__global__ void scan3_kernel(int E) {
    int i = blockIdx.x * blockDim.x + threadIdx.x;
    if (i < NNODES) {
        int r = g_rowptr[i] + g_blkoff[i >> 8];
        g_rowptr[i] = r;
        g_cursor[i] = r;
    }
    if (i == 0) g_rowptr[NNODES] = E;
}

// ---------------- permute edges into CSR ----------------
__global__ void permute_kernel(const void* __restrict__ ei, int E) {
    int e = blockIdx.x * blockDim.x + threadIdx.x;
    if (e >= E) return;
    int s = ld_idx(ei, e);
    int d = ld_idx(ei, (long long)E + e);
    float nm = g_dinv[s] * g_dinv[d];
    int pos = atomicAdd(&g_cursor[d], 1);
    g_esrc[pos] = s;
    g_enorm[pos] = nm;
}

// ---------------- GEMM1 (HMMA bf16 3-pass, ldmatrix): h1 = x @ W1 ----------------
#define SM1_TOTAL (4 * 128 * PAD * 2)
__global__ void __launch_bounds__(256) mma_gemm1(const float* __restrict__ x) {
    extern __shared__ __nv_bfloat16 sm[];
    const uint32_t sbase = (uint32_t)__cvta_generic_to_shared(sm);
    const uint32_t AHI = 0, ALO = 128 * PAD * 2, BHI = 2 * 128 * PAD * 2, BLO = 3 * 128 * PAD * 2;
    __nv_bfloat16* sAh = sm;
    __nv_bfloat16* sAl = sm + 128 * PAD;
    __nv_bfloat16* sBh = sm + 2 * 128 * PAD;
    __nv_bfloat16* sBl = sm + 3 * 128 * PAD;
    const int tid = threadIdx.x, wid = tid >> 5, lid = tid & 31;
    const int row0 = blockIdx.x * 128;

    // B: direct copy from presplit W1^T (128 rows x 16 uint4 chunks)
    for (int i = tid; i < 128 * 16; i += 256) {
        int r = i >> 4, c = i & 15;
        *(uint4*)&sBh[r * PAD + c * 8] = ((const uint4*)g_w1h)[r * 16 + c];
        *(uint4*)&sBl[r * PAD + c * 8] = ((const uint4*)g_w1l)[r * 16 + c];
    }
    // A: convert x fp32 -> hi/lo
    for (int i = tid; i < 128 * 64; i += 256) {
        int r = i >> 6, c = i & 63;
        int gr = row0 + r;
        float2 v = make_float2(0.f, 0.f);
        if (gr < NNODES) v = ((const float2*)x)[(size_t)gr * 64 + c];
        uint32_t hi, lo;
        split2_packed(v.x, v.y, hi, lo);
        *(uint32_t*)&sAh[r * PAD + c * 2] = hi;
        *(uint32_t*)&sAl[r * PAD + c * 2] = lo;
    }
    __syncthreads();

    const int wr = wid >> 1, wc = wid & 1;
    const int g = lid >> 2, tg = lid & 3;
    const int ar0 = wr * 32, nc0 = wc * 64;

    // ldmatrix per-lane offsets (bytes)
    const int m4 = lid >> 3;
    const int arow = (m4 & 1) * 8 + (lid & 7);
    const int acol = (m4 >> 1) * 8;
    const uint32_t offA0 = (uint32_t)(((ar0 + arow) * PAD + acol) * 2);
    const uint32_t offA1 = (uint32_t)(((ar0 + 16 + arow) * PAD + acol) * 2);
    const int brow = (m4 >> 1) * 8 + (lid & 7);
    const int bcol = (m4 & 1) * 8;
    uint32_t offB[4];
#pragma unroll
    for (int bi = 0; bi < 4; bi++)
        offB[bi] = (uint32_t)(((nc0 + bi * 16 + brow) * PAD + bcol) * 2);

    float acc[2][8][4];
#pragma unroll
    for (int mi = 0; mi < 2; mi++)
#pragma unroll
        for (int ni = 0; ni < 8; ni++)
#pragma unroll
            for (int j = 0; j < 4; j++) acc[mi][ni][j] = 0.f;

#pragma unroll 1
    for (int pass = 0; pass < 3; pass++) {
        uint32_t abase = sbase + ((pass == 2) ? ALO : AHI);
        uint32_t bbase = sbase + ((pass == 1) ? BLO : BHI);
#pragma unroll 1
        for (int ks = 0; ks < 8; ks++) {
            uint32_t kb = (uint32_t)ks * 32;
            uint32_t a0[4], a1[4];
            ldsm_x4(a0[0], a0[1], a0[2], a0[3], abase + offA0 + kb);
            ldsm_x4(a1[0], a1[1], a1[2], a1[3], abase + offA1 + kb);
#pragma unroll
            for (int bi = 0; bi < 4; bi++) {
                uint32_t b0, b1, b2, b3;
                ldsm_x4(b0, b1, b2, b3, bbase + offB[bi] + kb);
                mma_bf16(acc[0][2 * bi], a0, b0, b1);
                mma_bf16(acc[0][2 * bi + 1], a0, b2, b3);
                mma_bf16(acc[1][2 * bi], a1, b0, b1);
                mma_bf16(acc[1][2 * bi + 1], a1, b2, b3);
            }
        }
    }

#pragma unroll
    for (int mi = 0; mi < 2; mi++)
#pragma unroll
        for (int h = 0; h < 2; h++) {
            int r = row0 + ar0 + mi * 16 + g + h * 8;
            if (r < NNODES) {
#pragma unroll
                for (int ni = 0; ni < 8; ni++) {
                    int c = nc0 + ni * 8 + tg * 2;
                    *(float2*)&g_h1[(size_t)r * 128 + c] =
                        make_float2(acc[mi][ni][h * 2], acc[mi][ni][h * 2 + 1]);
                }
            }
        }
}

// ---------------- agg1: warp/node gather-reduce + BN + ReLU + bf16 split ----------------
__global__ void __launch_bounds__(256) agg1_kernel() {
    int w = (blockIdx.x * blockDim.x + threadIdx.x) >> 5;
    int lane = threadIdx.x & 31;
    if (w >= NNODES) return;
    int beg = g_rowptr[w], end = g_rowptr[w + 1];
    float di = g_dinv[w];
    float d2 = di * di;
    const float4* h1 = (const float4*)g_h1;
    float4 acc = h1[(size_t)w * 32 + lane];
    acc.x *= d2; acc.y *= d2; acc.z *= d2; acc.w *= d2;
    int j = beg;
    for (; j + 2 <= end; j += 2) {
        int s0 = g_esrc[j], s1 = g_esrc[j + 1];
        float n0 = g_enorm[j], n1 = g_enorm[j + 1];
        float4 v0 = h1[(size_t)s0 * 32 + lane];
        float4 v1 = h1[(size_t)s1 * 32 + lane];
        acc.x += v0.x * n0 + v1.x * n1;
        acc.y += v0.y * n0 + v1.y * n1;
        acc.z += v0.z * n0 + v1.z * n1;
        acc.w += v0.w * n0 + v1.w * n1;
    }
    if (j < end) {
        int s0 = g_esrc[j];
        float n0 = g_enorm[j];
        float4 v0 = h1[(size_t)s0 * 32 + lane];
        acc.x += v0.x * n0; acc.y += v0.y * n0; acc.z += v0.z * n0; acc.w += v0.w * n0;
    }
    // BN + ReLU + split
    float4 s4 = *(const float4*)&g_bns[lane * 4];
    float4 t4 = *(const float4*)&g_bnt[lane * 4];
    float b0 = fmaxf(acc.x * s4.x + t4.x, 0.f);
    float b1 = fmaxf(acc.y * s4.y + t4.y, 0.f);
    float b2 = fmaxf(acc.z * s4.z + t4.z, 0.f);
    float b3 = fmaxf(acc.w * s4.w + t4.w, 0.f);
    uint32_t hi0, lo0, hi1, lo1;
    split2_packed(b0, b1, hi0, lo0);
    split2_packed(b2, b3, hi1, lo1);
    *(uint2*)&g_a2h[(size_t)w * 64 + lane * 2] = make_uint2(hi0, hi1);
    *(uint2*)&g_a2l[(size_t)w * 64 + lane * 2] = make_uint2(lo0, lo1);
}

// ---------------- GEMM2 (HMMA bf16 3-pass, ldmatrix): h2 = bnrelu(agg1) @ W2 ----------------
#define SM2_TOTAL (2 * 128 * PAD * 2 + 2 * 64 * PAD * 2)
__global__ void __launch_bounds__(256) mma_gemm2() {
    extern __shared__ __nv_bfloat16 sm[];
    const uint32_t sbase = (uint32_t)__cvta_generic_to_shared(sm);
    const uint32_t AHI = 0, ALO = 128 * PAD * 2;
    const uint32_t BHI = 2 * 128 * PAD * 2, BLO = 2 * 128 * PAD * 2 + 64 * PAD * 2;
    __nv_bfloat16* sAh = sm;
    __nv_bfloat16* sAl = sm + 128 * PAD;
    __nv_bfloat16* sBh = sm + 2 * 128 * PAD;
    __nv_bfloat16* sBl = sm + 2 * 128 * PAD + 64 * PAD;
    const int tid = threadIdx.x, wid = tid >> 5, lid = tid & 31;
    const int row0 = blockIdx.x * 128;

    // B copy
    for (int i = tid; i < 64 * 16; i += 256) {
        int r = i >> 4, c = i & 15;
        *(uint4*)&sBh[r * PAD + c * 8] = ((const uint4*)g_w2h)[r * 16 + c];
        *(uint4*)&sBl[r * PAD + c * 8] = ((const uint4*)g_w2l)[r * 16 + c];
    }
    // A copy (presplit by agg1)
    for (int i = tid; i < 128 * 16; i += 256) {
        int r = i >> 4, c = i & 15;
        int gr = row0 + r;
        uint4 vh = make_uint4(0, 0, 0, 0), vl = make_uint4(0, 0, 0, 0);
        if (gr < NNODES) {
            vh = *(const uint4*)&g_a2h[(size_t)gr * 64 + c * 4];
            vl = *(const uint4*)&g_a2l[(size_t)gr * 64 + c * 4];
        }
        *(uint4*)&sAh[r * PAD + c * 8] = vh;
        *(uint4*)&sAl[r * PAD + c * 8] = vl;
    }
    __syncthreads();

    const int wr = wid >> 1, wc = wid & 1;
    const int g = lid >> 2, tg = lid & 3;
    const int ar0 = wr * 32, nc0 = wc * 32;

    const int m4 = lid >> 3;
    const int arow = (m4 & 1) * 8 + (lid & 7);
    const int acol = (m4 >> 1) * 8;
    const uint32_t offA0 = (uint32_t)(((ar0 + arow) * PAD + acol) * 2);
    const uint32_t offA1 = (uint32_t)(((ar0 + 16 + arow) * PAD + acol) * 2);
    const int brow = (m4 >> 1) * 8 + (lid & 7);
    const int bcol = (m4 & 1) * 8;
    uint32_t offB[2];
#pragma unroll
    for (int bi = 0; bi < 2; bi++)
        offB[bi] = (uint32_t)(((nc0 + bi * 16 + brow) * PAD + bcol) * 2);

    float acc[2][4][4];
#pragma unroll
    for (int mi = 0; mi < 2; mi++)
#pragma unroll
        for (int ni = 0; ni < 4; ni++)
#pragma unroll
            for (int j = 0; j < 4; j++) acc[mi][ni][j] = 0.f;

#pragma unroll 1
    for (int pass = 0; pass < 3; pass++) {
        uint32_t abase = sbase + ((pass == 2) ? ALO : AHI);
        uint32_t bbase = sbase + ((pass == 1) ? BLO : BHI);
#pragma unroll 1
        for (int ks = 0; ks < 8; ks++) {
            uint32_t kb = (uint32_t)ks * 32;
            uint32_t a0[4], a1[4];
            ldsm_x4(a0[0], a0[1], a0[2], a0[3], abase + offA0 + kb);
            ldsm_x4(a1[0], a1[1], a1[2], a1[3], abase + offA1 + kb);
#pragma unroll
            for (int bi = 0; bi < 2; bi++) {
                uint32_t b0, b1, b2, b3;
                ldsm_x4(b0, b1, b2, b3, bbase + offB[bi] + kb);
                mma_bf16(acc[0][2 * bi], a0, b0, b1);
                mma_bf16(acc[0][2 * bi + 1], a0, b2, b3);
                mma_bf16(acc[1][2 * bi], a1, b0, b1);
                mma_bf16(acc[1][2 * bi + 1], a1, b2, b3);
            }
        }
    }

#pragma unroll
    for (int mi = 0; mi < 2; mi++)
#pragma unroll
        for (int h = 0; h < 2; h++) {
            int r = row0 + ar0 + mi * 16 + g + h * 8;
            if (r < NNODES) {
#pragma unroll
                for (int ni = 0; ni < 4; ni++) {
                    int c = nc0 + ni * 8 + tg * 2;
                    *(float2*)&g_h2[(size_t)r * 64 + c] =
                        make_float2(acc[mi][ni][h * 2], acc[mi][ni][h * 2 + 1]);
                }
            }
        }
}

// ---------------- agg2: half-warp per node ----------------
__global__ void __launch_bounds__(256) agg2_kernel(const float* __restrict__ b2,
                                                   float* __restrict__ out) {
    int t = blockIdx.x * blockDim.x + threadIdx.x;
    int hw = t >> 4;
    int sub = t & 15;
    if (hw >= NNODES) return;
    int beg = g_rowptr[hw], end = g_rowptr[hw + 1];
    float di = g_dinv[hw];
    float d2 = di * di;
    const float4* h2 = (const float4*)g_h2;
    float4 acc = h2[(size_t)hw * 16 + sub];
    acc.x *= d2; acc.y *= d2; acc.z *= d2; acc.w *= d2;
    int j = beg;
    for (; j + 2 <= end; j += 2) {
        int s0 = g_esrc[j], s1 = g_esrc[j + 1];
        float n0 = g_enorm[j], n1 = g_enorm[j + 1];
        float4 v0 = h2[(size_t)s0 * 16 + sub];
        float4 v1 = h2[(size_t)s1 * 16 + sub];
        acc.x += v0.x * n0 + v1.x * n1;
        acc.y += v0.y * n0 + v1.y * n1;
        acc.z += v0.z * n0 + v1.z * n1;
        acc.w += v0.w * n0 + v1.w * n1;
    }
    if (j < end) {
        int s0 = g_esrc[j];
        float n0 = g_enorm[j];
        float4 v0 = h2[(size_t)s0 * 16 + sub];
        acc.x += v0.x * n0; acc.y += v0.y * n0; acc.z += v0.z * n0; acc.w += v0.w * n0;
    }
    float4 bv = ((const float4*)b2)[sub];
    ((float4*)out)[(size_t)hw * 16 + sub] =
        make_float4(acc.x + bv.x, acc.y + bv.y, acc.z + bv.z, acc.w + bv.w);
}

// ---------------- launch ----------------
extern "C" void kernel_launch(void* const* d_in, const int* in_sizes, int n_in,
                              void* d_out, int out_size) {
    const float* x     = (const float*)d_in[0];
    const void*  ei    = d_in[1];
    const float* W1    = (const float*)d_in[2];
    const float* b1    = (const float*)d_in[3];
    const float* gamma = (const float*)d_in[4];
    const float* beta  = (const float*)d_in[5];
    const float* rmean = (const float*)d_in[6];
    const float* rvar  = (const float*)d_in[7];
    const float* W2    = (const float*)d_in[8];
    const float* b2    = (const float*)d_in[9];
    float* out = (float*)d_out;

    const int E = in_sizes[1] / 2;

    cudaFuncSetAttribute(mma_gemm1, cudaFuncAttributeMaxDynamicSharedMemorySize, SM1_TOTAL);
    cudaFuncSetAttribute(mma_gemm2, cudaFuncAttributeMaxDynamicSharedMemorySize, SM2_TOTAL);

    int nblk = (NNODES + 255) / 256;  // 391
    init_kernel<<<nblk, 256>>>(ei);
    wsplit_kernel<<<64, 256>>>(W1, W2);
    deg_count_kernel<<<(E + 255) / 256, 256>>>(ei, E);
    dinv_bn_kernel<<<nblk, 256>>>(b1, gamma, beta, rmean, rvar);

    scan1_kernel<<<nblk, 256>>>();
    scan2_kernel<<<1, 512>>>(nblk);
    scan3_kernel<<<nblk, 256>>>(E);
    permute_kernel<<<(E + 255) / 256, 256>>>(ei, E);

    int gblk = (NNODES + 127) / 128;  // 782
    mma_gemm1<<<gblk, 256, SM1_TOTAL>>>(x);

    {
        long long th = (long long)NNODES * 32;
        agg1_kernel<<<(int)((th + 255) / 256), 256>>>();
    }

    mma_gemm2<<<gblk, 256, SM2_TOTAL>>>();

    {
        long long th = (long long)NNODES * 16;
        agg2_kernel<<<(int)((th + 255) / 256), 256>>>(b2, out);
    }
}

// round 7
// speedup vs baseline: 2.5619x; 1.1146x over previous
#include <cuda_runtime.h>
#include <cuda_bf16.h>
#include <stdint.h>

#define NNODES 100000
#define H1DIM 128
#define H2DIM 64
#define BN_EPS 1e-5f
#define PAD 136
#define EMAX (1 << 20)

// ---------------- scratch ----------------
__device__ int   g_degi[NNODES];
__device__ float g_dinv[NNODES];
__device__ int   g_rowptr[NNODES + 1];
__device__ int   g_cursor[NNODES];
__device__ int   g_blksum[512];
__device__ int   g_blkoff[512];
__device__ int   g_esrc[EMAX];
__device__ float g_enorm[EMAX];
__device__ uint32_t g_axh[(size_t)NNODES * 64];   // aggX hi bf16x2
__device__ uint32_t g_axl[(size_t)NNODES * 64];   // aggX lo bf16x2
__device__ float g_h2[(size_t)NNODES * H2DIM];
__device__ float g_bns[H1DIM];
__device__ float g_bnt[H1DIM];
__device__ __align__(16) __nv_bfloat16 g_w1h[128 * 128];  // W1^T hi  [n][k]
__device__ __align__(16) __nv_bfloat16 g_w1l[128 * 128];
__device__ __align__(16) __nv_bfloat16 g_w2h[64 * 128];   // W2^T hi
__device__ __align__(16) __nv_bfloat16 g_w2l[64 * 128];
__device__ int   g_is64;

// ---------------- helpers ----------------
__device__ __forceinline__ void mma_bf16(float* c, const uint32_t* a, uint32_t b0, uint32_t b1) {
    asm volatile("mma.sync.aligned.m16n8k16.row.col.f32.bf16.bf16.f32 "
                 "{%0,%1,%2,%3}, {%4,%5,%6,%7}, {%8,%9}, {%0,%1,%2,%3};"
                 : "+f"(c[0]), "+f"(c[1]), "+f"(c[2]), "+f"(c[3])
                 : "r"(a[0]), "r"(a[1]), "r"(a[2]), "r"(a[3]), "r"(b0), "r"(b1));
}
__device__ __forceinline__ void ldsm_x4(uint32_t& r0, uint32_t& r1, uint32_t& r2, uint32_t& r3,
                                        uint32_t addr) {
    asm volatile("ldmatrix.sync.aligned.m8n8.x4.shared.b16 {%0,%1,%2,%3}, [%4];"
                 : "=r"(r0), "=r"(r1), "=r"(r2), "=r"(r3) : "r"(addr));
}
__device__ __forceinline__ void split1(float v, __nv_bfloat16& hi, __nv_bfloat16& lo) {
    hi = __float2bfloat16_rn(v);
    lo = __float2bfloat16_rn(v - __bfloat162float(hi));
}
__device__ __forceinline__ void split2_packed(float a, float b, uint32_t& hi, uint32_t& lo) {
    __nv_bfloat16 ha, la, hb, lb;
    split1(a, ha, la);
    split1(b, hb, lb);
    hi = (uint32_t)__bfloat16_as_ushort(ha) | ((uint32_t)__bfloat16_as_ushort(hb) << 16);
    lo = (uint32_t)__bfloat16_as_ushort(la) | ((uint32_t)__bfloat16_as_ushort(lb) << 16);
}

// ---------------- init: zero degrees + detect edge dtype ----------------
__global__ void init_kernel(const void* ei) {
    int i = blockIdx.x * blockDim.x + threadIdx.x;
    if (i < NNODES) g_degi[i] = 0;
    if (i == 0) {
        const long long* p = (const long long*)ei;
        int is64 = 1;
        for (int j = 0; j < 64; j++) {
            long long v = p[j];
            if (v < 0 || v >= (long long)NNODES) { is64 = 0; break; }
        }
        g_is64 = is64;
    }
}
__device__ __forceinline__ int ld_idx(const void* p, long long i) {
    if (g_is64) return (int)((const long long*)p)[i];
    return ((const int*)p)[i];
}

// ---------------- W split (once) ----------------
__global__ void wsplit_kernel(const float* __restrict__ W1, const float* __restrict__ W2) {
    int i = blockIdx.x * blockDim.x + threadIdx.x;
    if (i < 128 * 128) {
        int k = i >> 7, n = i & 127;
        __nv_bfloat16 hb, lb;
        split1(W1[k * 128 + n], hb, lb);
        g_w1h[n * 128 + k] = hb;
        g_w1l[n * 128 + k] = lb;
    }
    if (i < 128 * 64) {
        int k = i >> 6, n = i & 63;
        __nv_bfloat16 hb, lb;
        split1(W2[k * 64 + n], hb, lb);
        g_w2h[n * 128 + k] = hb;
        g_w2l[n * 128 + k] = lb;
    }
}

// ---------------- degree / dinv / BN ----------------
__global__ void deg_count_kernel(const void* ei, int E) {
    int e = blockIdx.x * blockDim.x + threadIdx.x;
    if (e < E) atomicAdd(&g_degi[ld_idx(ei, (long long)E + e)], 1);
}
__global__ void dinv_bn_kernel(const float* __restrict__ b1,
                               const float* __restrict__ gamma,
                               const float* __restrict__ beta,
                               const float* __restrict__ rmean,
                               const float* __restrict__ rvar) {
    int i = blockIdx.x * blockDim.x + threadIdx.x;
    if (i < NNODES) g_dinv[i] = rsqrtf((float)g_degi[i] + 1.0f);
    if (i < H1DIM) {
        float s = gamma[i] * rsqrtf(rvar[i] + BN_EPS);
        g_bns[i] = s;
        g_bnt[i] = (b1[i] - rmean[i]) * s + beta[i];
    }
}

// ---------------- exclusive scan (3 kernels) ----------------
__global__ void scan1_kernel() {
    __shared__ int sm[256];
    int i = blockIdx.x * 256 + threadIdx.x;
    int v = (i < NNODES) ? g_degi[i] : 0;
    sm[threadIdx.x] = v;
    __syncthreads();
    for (int off = 1; off < 256; off <<= 1) {
        int t = (threadIdx.x >= off) ? sm[threadIdx.x - off] : 0;
        __syncthreads();
        sm[threadIdx.x] += t;
        __syncthreads();
    }
    if (i < NNODES) g_rowptr[i] = sm[threadIdx.x] - v;
    if (threadIdx.x == 255) g_blksum[blockIdx.x] = sm[255];
}
__global__ void scan2_kernel(int nb) {
    __shared__ int sm[512];
    int v = (threadIdx.x < nb) ? g_blksum[threadIdx.x] : 0;
    sm[threadIdx.x] = v;
    __syncthreads();
    for (int off = 1; off < 512; off <<= 1) {
        int t = (threadIdx.x >= off) ? sm[threadIdx.x - off] : 0;
        __syncthreads();
        sm[threadIdx.x] += t;
        __syncthreads();
    }
    if (threadIdx.x < nb) g_blkoff[threadIdx.x] = sm[threadIdx.x] - v;
}
__global__ void scan3_kernel(int E) {
    int i = blockIdx.x * blockDim.x + threadIdx.x;
    if (i < NNODES) {
        int r = g_rowptr[i] + g_blkoff[i >> 8];
        g_rowptr[i] = r;
        g_cursor[i] = r;
    }
    if (i == 0) g_rowptr[NNODES] = E;
}

// ---------------- permute edges into CSR ----------------
__global__ void permute_kernel(const void* __restrict__ ei, int E) {
    int e = blockIdx.x * blockDim.x + threadIdx.x;
    if (e >= E) return;
    int s = ld_idx(ei, e);
    int d = ld_idx(ei, (long long)E + e);
    float nm = g_dinv[s] * g_dinv[d];
    int pos = atomicAdd(&g_cursor[d], 1);
    g_esrc[pos] = s;
    g_enorm[pos] = nm;
}

// ---------------- aggX: warp/node gather-reduce over x + bf16 split ----------------
__global__ void __launch_bounds__(256) aggx_kernel(const float* __restrict__ x) {
    int w = (blockIdx.x * blockDim.x + threadIdx.x) >> 5;
    int lane = threadIdx.x & 31;
    if (w >= NNODES) return;
    int beg = g_rowptr[w], end = g_rowptr[w + 1];
    float di = g_dinv[w];
    float d2 = di * di;
    const float4* xr = (const float4*)x;
    float4 acc = xr[(size_t)w * 32 + lane];
    acc.x *= d2; acc.y *= d2; acc.z *= d2; acc.w *= d2;
    int j = beg;
    for (; j + 4 <= end; j += 4) {
        int s0 = g_esrc[j], s1 = g_esrc[j + 1], s2 = g_esrc[j + 2], s3 = g_esrc[j + 3];
        float n0 = g_enorm[j], n1 = g_enorm[j + 1], n2 = g_enorm[j + 2], n3 = g_enorm[j + 3];
        float4 v0 = xr[(size_t)s0 * 32 + lane];
        float4 v1 = xr[(size_t)s1 * 32 + lane];
        float4 v2 = xr[(size_t)s2 * 32 + lane];
        float4 v3 = xr[(size_t)s3 * 32 + lane];
        acc.x += v0.x * n0 + v1.x * n1 + v2.x * n2 + v3.x * n3;
        acc.y += v0.y * n0 + v1.y * n1 + v2.y * n2 + v3.y * n3;
        acc.z += v0.z * n0 + v1.z * n1 + v2.z * n2 + v3.z * n3;
        acc.w += v0.w * n0 + v1.w * n1 + v2.w * n2 + v3.w * n3;
    }
    for (; j < end; j++) {
        int s0 = g_esrc[j];
        float n0 = g_enorm[j];
        float4 v0 = xr[(size_t)s0 * 32 + lane];
        acc.x += v0.x * n0; acc.y += v0.y * n0; acc.z += v0.z * n0; acc.w += v0.w * n0;
    }
    uint32_t hi0, lo0, hi1, lo1;
    split2_packed(acc.x, acc.y, hi0, lo0);
    split2_packed(acc.z, acc.w, hi1, lo1);
    *(uint2*)&g_axh[(size_t)w * 64 + lane * 2] = make_uint2(hi0, hi1);
    *(uint2*)&g_axl[(size_t)w * 64 + lane * 2] = make_uint2(lo0, lo1);
}

// ---------------- fused GEMM: h2 = bnrelu(aggx @ W1) @ W2 ----------------
// smem planes (bf16 elems): A hi/lo 128xPAD, W1 hi/lo 128xPAD, W2 hi/lo 64xPAD.
// After MMA1, A planes are overwritten with H = bnrelu(...) hi/lo.
#define SMF_AHI 0
#define SMF_ALO (128 * PAD)
#define SMF_W1H (2 * 128 * PAD)
#define SMF_W1L (3 * 128 * PAD)
#define SMF_W2H (4 * 128 * PAD)
#define SMF_W2L (4 * 128 * PAD + 64 * PAD)
#define SMF_TOTAL ((4 * 128 * PAD + 2 * 64 * PAD) * 2)

__global__ void __launch_bounds__(256) fused_gemm_kernel() {
    extern __shared__ __nv_bfloat16 sm[];
    const uint32_t sbase = (uint32_t)__cvta_generic_to_shared(sm);
    const int tid = threadIdx.x, wid = tid >> 5, lid = tid & 31;
    const int row0 = blockIdx.x * 128;

    // W1 copy (128 rows x 16 uint4)
    for (int i = tid; i < 128 * 16; i += 256) {
        int r = i >> 4, c = i & 15;
        *(uint4*)&sm[SMF_W1H + r * PAD + c * 8] = ((const uint4*)g_w1h)[r * 16 + c];
        *(uint4*)&sm[SMF_W1L + r * PAD + c * 8] = ((const uint4*)g_w1l)[r * 16 + c];
    }
    // W2 copy (64 rows x 16 uint4)
    for (int i = tid; i < 64 * 16; i += 256) {
        int r = i >> 4, c = i & 15;
        *(uint4*)&sm[SMF_W2H + r * PAD + c * 8] = ((const uint4*)g_w2h)[r * 16 + c];
        *(uint4*)&sm[SMF_W2L + r * PAD + c * 8] = ((const uint4*)g_w2l)[r * 16 + c];
    }
    // A copy (presplit aggx)
    for (int i = tid; i < 128 * 16; i += 256) {
        int r = i >> 4, c = i & 15;
        int gr = row0 + r;
        uint4 vh = make_uint4(0, 0, 0, 0), vl = make_uint4(0, 0, 0, 0);
        if (gr < NNODES) {
            vh = *(const uint4*)&g_axh[(size_t)gr * 64 + c * 4];
            vl = *(const uint4*)&g_axl[(size_t)gr * 64 + c * 4];
        }
        *(uint4*)&sm[SMF_AHI + r * PAD + c * 8] = vh;
        *(uint4*)&sm[SMF_ALO + r * PAD + c * 8] = vl;
    }
    __syncthreads();

    const int wr = wid >> 1, wc = wid & 1;
    const int g = lid >> 2, tg = lid & 3;
    const int ar0 = wr * 32;

    // ldmatrix lane offsets (in bf16 elements; *2 for bytes)
    const int m4 = lid >> 3;
    const int arow = (m4 & 1) * 8 + (lid & 7);
    const int acol = (m4 >> 1) * 8;
    const uint32_t offA0 = (uint32_t)(((ar0 + arow) * PAD + acol) * 2);
    const uint32_t offA1 = (uint32_t)(((ar0 + 16 + arow) * PAD + acol) * 2);
    const int brow = (m4 >> 1) * 8 + (lid & 7);
    const int bcol = (m4 & 1) * 8;

    // ---------- MMA1: 128x128, warp tile 32x64 at (ar0, nc1) ----------
    {
        const int nc1 = wc * 64;
        uint32_t offB[4];
#pragma unroll
        for (int bi = 0; bi < 4; bi++)
            offB[bi] = (uint32_t)(((nc1 + bi * 16 + brow) * PAD + bcol) * 2);

        float acc[2][8][4];
#pragma unroll
        for (int mi = 0; mi < 2; mi++)
#pragma unroll
            for (int ni = 0; ni < 8; ni++)
#pragma unroll
                for (int j = 0; j < 4; j++) acc[mi][ni][j] = 0.f;

#pragma unroll 1
        for (int pass = 0; pass < 3; pass++) {
            uint32_t abase = sbase + 2 * ((pass == 2) ? SMF_ALO : SMF_AHI);
            uint32_t bbase = sbase + 2 * ((pass == 1) ? SMF_W1L : SMF_W1H);
#pragma unroll 1
            for (int ks = 0; ks < 8; ks++) {
                uint32_t kb = (uint32_t)ks * 32;
                uint32_t a0[4], a1[4];
                ldsm_x4(a0[0], a0[1], a0[2], a0[3], abase + offA0 + kb);
                ldsm_x4(a1[0], a1[1], a1[2], a1[3], abase + offA1 + kb);
#pragma unroll
                for (int bi = 0; bi < 4; bi++) {
                    uint32_t b0, b1, b2, b3;
                    ldsm_x4(b0, b1, b2, b3, bbase + offB[bi] + kb);
                    mma_bf16(acc[0][2 * bi], a0, b0, b1);
                    mma_bf16(acc[0][2 * bi + 1], a0, b2, b3);
                    mma_bf16(acc[1][2 * bi], a1, b0, b1);
                    mma_bf16(acc[1][2 * bi + 1], a1, b2, b3);
                }
            }
        }

        __syncthreads();  // all warps done reading A before overwrite

        // BN + ReLU + split -> H into A planes
#pragma unroll
        for (int mi = 0; mi < 2; mi++)
#pragma unroll
            for (int h = 0; h < 2; h++) {
                int rl = ar0 + mi * 16 + h * 8 + g;
#pragma unroll
                for (int ni = 0; ni < 8; ni++) {
                    int c = nc1 + ni * 8 + tg * 2;
                    float2 sc = *(const float2*)&g_bns[c];
                    float2 tc = *(const float2*)&g_bnt[c];
                    float v0 = fmaxf(acc[mi][ni][h * 2] * sc.x + tc.x, 0.f);
                    float v1 = fmaxf(acc[mi][ni][h * 2 + 1] * sc.y + tc.y, 0.f);
                    uint32_t hi, lo;
                    split2_packed(v0, v1, hi, lo);
                    *(uint32_t*)&sm[SMF_AHI + rl * PAD + c] = hi;
                    *(uint32_t*)&sm[SMF_ALO + rl * PAD + c] = lo;
                }
            }
    }
    __syncthreads();

    // ---------- MMA2: 128x64, warp tile 32x32 at (ar0, nc2) ----------
    {
        const int nc2 = wc * 32;
        uint32_t offB[2];
#pragma unroll
        for (int bi = 0; bi < 2; bi++)
            offB[bi] = (uint32_t)(((nc2 + bi * 16 + brow) * PAD + bcol) * 2);

        float acc[2][4][4];
#pragma unroll
        for (int mi = 0; mi < 2; mi++)
#pragma unroll
            for (int ni = 0; ni < 4; ni++)
#pragma unroll
                for (int j = 0; j < 4; j++) acc[mi][ni][j] = 0.f;

#pragma unroll 1
        for (int pass = 0; pass < 3; pass++) {
            uint32_t abase = sbase + 2 * ((pass == 2) ? SMF_ALO : SMF_AHI);
            uint32_t bbase = sbase + 2 * ((pass == 1) ? SMF_W2L : SMF_W2H);
#pragma unroll 1
            for (int ks = 0; ks < 8; ks++) {
                uint32_t kb = (uint32_t)ks * 32;
                uint32_t a0[4], a1[4];
                ldsm_x4(a0[0], a0[1], a0[2], a0[3], abase + offA0 + kb);
                ldsm_x4(a1[0], a1[1], a1[2], a1[3], abase + offA1 + kb);
#pragma unroll
                for (int bi = 0; bi < 2; bi++) {
                    uint32_t b0, b1, b2, b3;
                    ldsm_x4(b0, b1, b2, b3, bbase + offB[bi] + kb);
                    mma_bf16(acc[0][2 * bi], a0, b0, b1);
                    mma_bf16(acc[0][2 * bi + 1], a0, b2, b3);
                    mma_bf16(acc[1][2 * bi], a1, b0, b1);
                    mma_bf16(acc[1][2 * bi + 1], a1, b2, b3);
                }
            }
        }

#pragma unroll
        for (int mi = 0; mi < 2; mi++)
#pragma unroll
            for (int h = 0; h < 2; h++) {
                int r = row0 + ar0 + mi * 16 + g + h * 8;
                if (r < NNODES) {
#pragma unroll
                    for (int ni = 0; ni < 4; ni++) {
                        int c = nc2 + ni * 8 + tg * 2;
                        *(float2*)&g_h2[(size_t)r * 64 + c] =
                            make_float2(acc[mi][ni][h * 2], acc[mi][ni][h * 2 + 1]);
                    }
                }
            }
    }
}

// ---------------- agg2: half-warp per node ----------------
__global__ void __launch_bounds__(256) agg2_kernel(const float* __restrict__ b2,
                                                   float* __restrict__ out) {
    int t = blockIdx.x * blockDim.x + threadIdx.x;
    int hw = t >> 4;
    int sub = t & 15;
    if (hw >= NNODES) return;
    int beg = g_rowptr[hw], end = g_rowptr[hw + 1];
    float di = g_dinv[hw];
    float d2 = di * di;
    const float4* h2 = (const float4*)g_h2;
    float4 acc = h2[(size_t)hw * 16 + sub];
    acc.x *= d2; acc.y *= d2; acc.z *= d2; acc.w *= d2;
    int j = beg;
    for (; j + 4 <= end; j += 4) {
        int s0 = g_esrc[j], s1 = g_esrc[j + 1], s2 = g_esrc[j + 2], s3 = g_esrc[j + 3];
        float n0 = g_enorm[j], n1 = g_enorm[j + 1], n2 = g_enorm[j + 2], n3 = g_enorm[j + 3];
        float4 v0 = h2[(size_t)s0 * 16 + sub];
        float4 v1 = h2[(size_t)s1 * 16 + sub];
        float4 v2 = h2[(size_t)s2 * 16 + sub];
        float4 v3 = h2[(size_t)s3 * 16 + sub];
        acc.x += v0.x * n0 + v1.x * n1 + v2.x * n2 + v3.x * n3;
        acc.y += v0.y * n0 + v1.y * n1 + v2.y * n2 + v3.y * n3;
        acc.z += v0.z * n0 + v1.z * n1 + v2.z * n2 + v3.z * n3;
        acc.w += v0.w * n0 + v1.w * n1 + v2.w * n2 + v3.w * n3;
    }
    for (; j < end; j++) {
        int s0 = g_esrc[j];
        float n0 = g_enorm[j];
        float4 v0 = h2[(size_t)s0 * 16 + sub];
        acc.x += v0.x * n0; acc.y += v0.y * n0; acc.z += v0.z * n0; acc.w += v0.w * n0;
    }
    float4 bv = ((const float4*)b2)[sub];
    ((float4*)out)[(size_t)hw * 16 + sub] =
        make_float4(acc.x + bv.x, acc.y + bv.y, acc.z + bv.z, acc.w + bv.w);
}

// ---------------- launch ----------------
extern "C" void kernel_launch(void* const* d_in, const int* in_sizes, int n_in,
                              void* d_out, int out_size) {
    const float* x     = (const float*)d_in[0];
    const void*  ei    = d_in[1];
    const float* W1    = (const float*)d_in[2];
    const float* b1    = (const float*)d_in[3];
    const float* gamma = (const float*)d_in[4];
    const float* beta  = (const float*)d_in[5];
    const float* rmean = (const float*)d_in[6];
    const float* rvar  = (const float*)d_in[7];
    const float* W2    = (const float*)d_in[8];
    const float* b2    = (const float*)d_in[9];
    float* out = (float*)d_out;

    const int E = in_sizes[1] / 2;

    cudaFuncSetAttribute(fused_gemm_kernel, cudaFuncAttributeMaxDynamicSharedMemorySize, SMF_TOTAL);

    int nblk = (NNODES + 255) / 256;  // 391
    init_kernel<<<nblk, 256>>>(ei);
    wsplit_kernel<<<64, 256>>>(W1, W2);
    deg_count_kernel<<<(E + 255) / 256, 256>>>(ei, E);
    dinv_bn_kernel<<<nblk, 256>>>(b1, gamma, beta, rmean, rvar);

    scan1_kernel<<<nblk, 256>>>();
    scan2_kernel<<<1, 512>>>(nblk);
    scan3_kernel<<<nblk, 256>>>(E);
    permute_kernel<<<(E + 255) / 256, 256>>>(ei, E);

    // aggX: 1 warp/node
    {
        long long th = (long long)NNODES * 32;
        aggx_kernel<<<(int)((th + 255) / 256), 256>>>(x);
    }

    int gblk = (NNODES + 127) / 128;  // 782
    fused_gemm_kernel<<<gblk, 256, SMF_TOTAL>>>();

    // agg2: 1 half-warp/node
    {
        long long th = (long long)NNODES * 16;
        agg2_kernel<<<(int)((th + 255) / 256), 256>>>(b2, out);
    }
}

// round 8
// speedup vs baseline: 2.6397x; 1.0303x over previous
#include <cuda_runtime.h>
#include <cuda_bf16.h>
#include <stdint.h>

#define NNODES 100000
#define H1DIM 128
#define H2DIM 64
#define BN_EPS 1e-5f
#define PAD 136
#define EMAX (1 << 20)

// ---------------- scratch ----------------
__device__ int   g_degi[NNODES];
__device__ float g_dinv[NNODES];
__device__ int   g_rowptr[NNODES + 2];
__device__ int   g_cursor[NNODES];
__device__ int   g_blksum[512];
__device__ int   g_blkoff[512];
__device__ int   g_esrc[EMAX];
__device__ float g_enorm[EMAX];
__device__ float g_h2[(size_t)NNODES * H2DIM];
__device__ float g_bns[H1DIM];
__device__ float g_bnt[H1DIM];
__device__ __align__(16) __nv_bfloat16 g_w1h[128 * 128];  // W1^T hi  [n][k]
__device__ __align__(16) __nv_bfloat16 g_w1l[128 * 128];
__device__ __align__(16) __nv_bfloat16 g_w2h[64 * 128];   // W2^T hi
__device__ __align__(16) __nv_bfloat16 g_w2l[64 * 128];
__device__ int   g_is64;

// ---------------- helpers ----------------
__device__ __forceinline__ void mma_bf16(float* c, const uint32_t* a, uint32_t b0, uint32_t b1) {
    asm volatile("mma.sync.aligned.m16n8k16.row.col.f32.bf16.bf16.f32 "
                 "{%0,%1,%2,%3}, {%4,%5,%6,%7}, {%8,%9}, {%0,%1,%2,%3};"
                 : "+f"(c[0]), "+f"(c[1]), "+f"(c[2]), "+f"(c[3])
                 : "r"(a[0]), "r"(a[1]), "r"(a[2]), "r"(a[3]), "r"(b0), "r"(b1));
}
__device__ __forceinline__ void ldsm_x4(uint32_t& r0, uint32_t& r1, uint32_t& r2, uint32_t& r3,
                                        uint32_t addr) {
    asm volatile("ldmatrix.sync.aligned.m8n8.x4.shared.b16 {%0,%1,%2,%3}, [%4];"
                 : "=r"(r0), "=r"(r1), "=r"(r2), "=r"(r3) : "r"(addr));
}
__device__ __forceinline__ void split1(float v, __nv_bfloat16& hi, __nv_bfloat16& lo) {
    hi = __float2bfloat16_rn(v);
    lo = __float2bfloat16_rn(v - __bfloat162float(hi));
}
__device__ __forceinline__ void split2_packed(float a, float b, uint32_t& hi, uint32_t& lo) {
    __nv_bfloat16 ha, la, hb, lb;
    split1(a, ha, la);
    split1(b, hb, lb);
    hi = (uint32_t)__bfloat16_as_ushort(ha) | ((uint32_t)__bfloat16_as_ushort(hb) << 16);
    lo = (uint32_t)__bfloat16_as_ushort(la) | ((uint32_t)__bfloat16_as_ushort(lb) << 16);
}
__device__ __forceinline__ int ld_idx(const void* p, long long i) {
    if (g_is64) return (int)((const long long*)p)[i];
    return ((const int*)p)[i];
}

// ---------------- init: zero deg + detect dtype + W split ----------------
__global__ void initw_kernel(const void* ei, const float* __restrict__ W1,
                             const float* __restrict__ W2) {
    int i = blockIdx.x * blockDim.x + threadIdx.x;
    if (i < NNODES) g_degi[i] = 0;
    if (i == 0) {
        const long long* p = (const long long*)ei;
        int is64 = 1;
        for (int j = 0; j < 64; j++) {
            long long v = p[j];
            if (v < 0 || v >= (long long)NNODES) { is64 = 0; break; }
        }
        g_is64 = is64;
    }
    if (i < 128 * 128) {
        int k = i >> 7, n = i & 127;
        __nv_bfloat16 hb, lb;
        split1(W1[k * 128 + n], hb, lb);
        g_w1h[n * 128 + k] = hb;
        g_w1l[n * 128 + k] = lb;
    }
    if (i < 128 * 64) {
        int k = i >> 6, n = i & 63;
        __nv_bfloat16 hb, lb;
        split1(W2[k * 64 + n], hb, lb);
        g_w2h[n * 128 + k] = hb;
        g_w2l[n * 128 + k] = lb;
    }
}

__global__ void deg_count_kernel(const void* ei, int E) {
    int e = blockIdx.x * blockDim.x + threadIdx.x;
    if (e < E) atomicAdd(&g_degi[ld_idx(ei, (long long)E + e)], 1);
}

// ---------------- dinv + BN coeffs + scan phase 1 ----------------
__global__ void dinv_scan1_kernel(const float* __restrict__ b1,
                                  const float* __restrict__ gamma,
                                  const float* __restrict__ beta,
                                  const float* __restrict__ rmean,
                                  const float* __restrict__ rvar) {
    __shared__ int sm[256];
    int i = blockIdx.x * 256 + threadIdx.x;
    int v = (i < NNODES) ? g_degi[i] : 0;
    if (i < NNODES) g_dinv[i] = rsqrtf((float)v + 1.0f);
    if (i < H1DIM) {
        float s = gamma[i] * rsqrtf(rvar[i] + BN_EPS);
        g_bns[i] = s;
        g_bnt[i] = (b1[i] - rmean[i]) * s + beta[i];
    }
    sm[threadIdx.x] = v;
    __syncthreads();
    for (int off = 1; off < 256; off <<= 1) {
        int t = (threadIdx.x >= off) ? sm[threadIdx.x - off] : 0;
        __syncthreads();
        sm[threadIdx.x] += t;
        __syncthreads();
    }
    if (i < NNODES) g_rowptr[i] = sm[threadIdx.x] - v;
    if (threadIdx.x == 255) g_blksum[blockIdx.x] = sm[255];
}
__global__ void scan2_kernel(int nb) {
    __shared__ int sm[512];
    int v = (threadIdx.x < nb) ? g_blksum[threadIdx.x] : 0;
    sm[threadIdx.x] = v;
    __syncthreads();
    for (int off = 1; off < 512; off <<= 1) {
        int t = (threadIdx.x >= off) ? sm[threadIdx.x - off] : 0;
        __syncthreads();
        sm[threadIdx.x] += t;
        __syncthreads();
    }
    if (threadIdx.x < nb) g_blkoff[threadIdx.x] = sm[threadIdx.x] - v;
}
__global__ void scan3_kernel(int E) {
    int i = blockIdx.x * blockDim.x + threadIdx.x;
    if (i < NNODES) {
        int r = g_rowptr[i] + g_blkoff[i >> 8];
        g_rowptr[i] = r;
        g_cursor[i] = r;
    }
    if (i == 0) { g_rowptr[NNODES] = E; g_rowptr[NNODES + 1] = E; }
}
__global__ void permute_kernel(const void* __restrict__ ei, int E) {
    int e = blockIdx.x * blockDim.x + threadIdx.x;
    if (e >= E) return;
    int s = ld_idx(ei, e);
    int d = ld_idx(ei, (long long)E + e);
    float nm = g_dinv[s] * g_dinv[d];
    int pos = atomicAdd(&g_cursor[d], 1);
    g_esrc[pos] = s;
    g_enorm[pos] = nm;
}

// ---------------- fused: gather(x) -> MMA1 -> BN/ReLU -> MMA2 -> h2 ----------------
// 512 threads = 16 warps. smem planes (bf16 elems):
#define SMF_AHI 0
#define SMF_ALO (128 * PAD)
#define SMF_W1H (2 * 128 * PAD)
#define SMF_W1L (3 * 128 * PAD)
#define SMF_W2H (4 * 128 * PAD)
#define SMF_W2L (4 * 128 * PAD + 64 * PAD)
#define SMF_TOTAL ((4 * 128 * PAD + 2 * 64 * PAD) * 2)

__global__ void __launch_bounds__(512) fused_kernel(const float* __restrict__ x) {
    extern __shared__ __nv_bfloat16 sm[];
    const uint32_t sbase = (uint32_t)__cvta_generic_to_shared(sm);
    const int tid = threadIdx.x, wid = tid >> 5, lid = tid & 31;
    const int row0 = blockIdx.x * 128;

    // W copies
    for (int i = tid; i < 128 * 16; i += 512) {
        int r = i >> 4, c = i & 15;
        *(uint4*)&sm[SMF_W1H + r * PAD + c * 8] = ((const uint4*)g_w1h)[r * 16 + c];
        *(uint4*)&sm[SMF_W1L + r * PAD + c * 8] = ((const uint4*)g_w1l)[r * 16 + c];
    }
    for (int i = tid; i < 64 * 16; i += 512) {
        int r = i >> 4, c = i & 15;
        *(uint4*)&sm[SMF_W2H + r * PAD + c * 8] = ((const uint4*)g_w2h)[r * 16 + c];
        *(uint4*)&sm[SMF_W2L + r * PAD + c * 8] = ((const uint4*)g_w2l)[r * 16 + c];
    }

    // ---- gather phase: warp handles 8 local rows (node pairs; CSR rows contiguous) ----
    const float4* xr = (const float4*)x;
#pragma unroll 1
    for (int pair = 0; pair < 4; pair++) {
        int rl0 = wid * 8 + pair * 2;
        int n0 = row0 + rl0, n1 = n0 + 1;
        float4 acc0 = make_float4(0.f, 0.f, 0.f, 0.f);
        float4 acc1 = make_float4(0.f, 0.f, 0.f, 0.f);
        int beg0 = 0, end0 = 0, end1 = 0;
        if (n0 < NNODES) {
            beg0 = g_rowptr[n0];
            end0 = g_rowptr[n0 + 1];
            end1 = g_rowptr[n0 + 2];   // safe: rowptr[NNODES+1] defined
            float di0 = g_dinv[n0];
            acc0 = xr[(size_t)n0 * 32 + lid];
            acc0.x *= di0 * di0; acc0.y *= di0 * di0; acc0.z *= di0 * di0; acc0.w *= di0 * di0;
            if (n1 < NNODES) {
                float di1 = g_dinv[n1];
                acc1 = xr[(size_t)n1 * 32 + lid];
                acc1.x *= di1 * di1; acc1.y *= di1 * di1; acc1.z *= di1 * di1; acc1.w *= di1 * di1;
            } else {
                end1 = end0;
            }
        }
        int j = beg0;
        for (; j + 4 <= end1; j += 4) {
            int s0 = g_esrc[j], s1 = g_esrc[j + 1], s2 = g_esrc[j + 2], s3 = g_esrc[j + 3];
            float m0 = g_enorm[j], m1 = g_enorm[j + 1], m2 = g_enorm[j + 2], m3 = g_enorm[j + 3];
            float4 v0 = xr[(size_t)s0 * 32 + lid];
            float4 v1 = xr[(size_t)s1 * 32 + lid];
            float4 v2 = xr[(size_t)s2 * 32 + lid];
            float4 v3 = xr[(size_t)s3 * 32 + lid];
            float4* a0 = (j + 0 < end0) ? &acc0 : &acc1;
            float4* a1 = (j + 1 < end0) ? &acc0 : &acc1;
            float4* a2 = (j + 2 < end0) ? &acc0 : &acc1;
            float4* a3 = (j + 3 < end0) ? &acc0 : &acc1;
            a0->x += v0.x * m0; a0->y += v0.y * m0; a0->z += v0.z * m0; a0->w += v0.w * m0;
            a1->x += v1.x * m1; a1->y += v1.y * m1; a1->z += v1.z * m1; a1->w += v1.w * m1;
            a2->x += v2.x * m2; a2->y += v2.y * m2; a2->z += v2.z * m2; a2->w += v2.w * m2;
            a3->x += v3.x * m3; a3->y += v3.y * m3; a3->z += v3.z * m3; a3->w += v3.w * m3;
        }
        for (; j < end1; j++) {
            int s0 = g_esrc[j];
            float m0 = g_enorm[j];
            float4 v0 = xr[(size_t)s0 * 32 + lid];
            float4* a = (j < end0) ? &acc0 : &acc1;
            a->x += v0.x * m0; a->y += v0.y * m0; a->z += v0.z * m0; a->w += v0.w * m0;
        }
        // split + store both rows
        uint32_t h0a, l0a, h0b, l0b;
        split2_packed(acc0.x, acc0.y, h0a, l0a);
        split2_packed(acc0.z, acc0.w, h0b, l0b);
        *(uint2*)&sm[SMF_AHI + rl0 * PAD + lid * 4] = make_uint2(h0a, h0b);
        *(uint2*)&sm[SMF_ALO + rl0 * PAD + lid * 4] = make_uint2(l0a, l0b);
        uint32_t h1a, l1a, h1b, l1b;
        split2_packed(acc1.x, acc1.y, h1a, l1a);
        split2_packed(acc1.z, acc1.w, h1b, l1b);
        *(uint2*)&sm[SMF_AHI + (rl0 + 1) * PAD + lid * 4] = make_uint2(h1a, h1b);
        *(uint2*)&sm[SMF_ALO + (rl0 + 1) * PAD + lid * 4] = make_uint2(l1a, l1b);
    }
    __syncthreads();

    // warp grid 4x4
    const int wr = wid >> 2, wc = wid & 3;
    const int g = lid >> 2, tg = lid & 3;
    const int ar0 = wr * 32;

    const int m4 = lid >> 3;
    const int arow = (m4 & 1) * 8 + (lid & 7);
    const int acol = (m4 >> 1) * 8;
    const uint32_t offA0 = (uint32_t)(((ar0 + arow) * PAD + acol) * 2);
    const uint32_t offA1 = (uint32_t)(((ar0 + 16 + arow) * PAD + acol) * 2);
    const int brow = (m4 >> 1) * 8 + (lid & 7);
    const int bcol = (m4 & 1) * 8;

    // ---------- MMA1: warp tile 32x32 at (ar0, nc1) ----------
    {
        const int nc1 = wc * 32;
        uint32_t offB[2];
#pragma unroll
        for (int bi = 0; bi < 2; bi++)
            offB[bi] = (uint32_t)(((nc1 + bi * 16 + brow) * PAD + bcol) * 2);

        float acc[2][4][4];
#pragma unroll
        for (int mi = 0; mi < 2; mi++)
#pragma unroll
            for (int ni = 0; ni < 4; ni++)
#pragma unroll
                for (int j = 0; j < 4; j++) acc[mi][ni][j] = 0.f;

#pragma unroll 1
        for (int pass = 0; pass < 3; pass++) {
            uint32_t abase = sbase + 2 * ((pass == 2) ? SMF_ALO : SMF_AHI);
            uint32_t bbase = sbase + 2 * ((pass == 1) ? SMF_W1L : SMF_W1H);
#pragma unroll 1
            for (int ks = 0; ks < 8; ks++) {
                uint32_t kb = (uint32_t)ks * 32;
                uint32_t a0[4], a1[4];
                ldsm_x4(a0[0], a0[1], a0[2], a0[3], abase + offA0 + kb);
                ldsm_x4(a1[0], a1[1], a1[2], a1[3], abase + offA1 + kb);
#pragma unroll
                for (int bi = 0; bi < 2; bi++) {
                    uint32_t b0, b1, b2, b3;
                    ldsm_x4(b0, b1, b2, b3, bbase + offB[bi] + kb);
                    mma_bf16(acc[0][2 * bi], a0, b0, b1);
                    mma_bf16(acc[0][2 * bi + 1], a0, b2, b3);
                    mma_bf16(acc[1][2 * bi], a1, b0, b1);
                    mma_bf16(acc[1][2 * bi + 1], a1, b2, b3);
                }
            }
        }

        __syncthreads();

        // BN + ReLU + split -> H into A planes
#pragma unroll
        for (int mi = 0; mi < 2; mi++)
#pragma unroll
            for (int h = 0; h < 2; h++) {
                int rl = ar0 + mi * 16 + h * 8 + g;
#pragma unroll
                for (int ni = 0; ni < 4; ni++) {
                    int c = nc1 + ni * 8 + tg * 2;
                    float2 sc = *(const float2*)&g_bns[c];
                    float2 tc = *(const float2*)&g_bnt[c];
                    float v0 = fmaxf(acc[mi][ni][h * 2] * sc.x + tc.x, 0.f);
                    float v1 = fmaxf(acc[mi][ni][h * 2 + 1] * sc.y + tc.y, 0.f);
                    uint32_t hi, lo;
                    split2_packed(v0, v1, hi, lo);
                    *(uint32_t*)&sm[SMF_AHI + rl * PAD + c] = hi;
                    *(uint32_t*)&sm[SMF_ALO + rl * PAD + c] = lo;
                }
            }
    }
    __syncthreads();

    // ---------- MMA2: warp tile 32x16 at (ar0, nc2) ----------
    {
        const int nc2 = wc * 16;
        const uint32_t offB0 = (uint32_t)(((nc2 + brow) * PAD + bcol) * 2);

        float acc[2][2][4];
#pragma unroll
        for (int mi = 0; mi < 2; mi++)
#pragma unroll
            for (int ni = 0; ni < 2; ni++)
#pragma unroll
                for (int j = 0; j < 4; j++) acc[mi][ni][j] = 0.f;

#pragma unroll 1
        for (int pass = 0; pass < 3; pass++) {
            uint32_t abase = sbase + 2 * ((pass == 2) ? SMF_ALO : SMF_AHI);
            uint32_t bbase = sbase + 2 * ((pass == 1) ? SMF_W2L : SMF_W2H);
#pragma unroll 1
            for (int ks = 0; ks < 8; ks++) {
                uint32_t kb = (uint32_t)ks * 32;
                uint32_t a0[4], a1[4];
                ldsm_x4(a0[0], a0[1], a0[2], a0[3], abase + offA0 + kb);
                ldsm_x4(a1[0], a1[1], a1[2], a1[3], abase + offA1 + kb);
                uint32_t b0, b1, b2, b3;
                ldsm_x4(b0, b1, b2, b3, bbase + offB0 + kb);
                mma_bf16(acc[0][0], a0, b0, b1);
                mma_bf16(acc[0][1], a0, b2, b3);
                mma_bf16(acc[1][0], a1, b0, b1);
                mma_bf16(acc[1][1], a1, b2, b3);
            }
        }

#pragma unroll
        for (int mi = 0; mi < 2; mi++)
#pragma unroll
            for (int h = 0; h < 2; h++) {
                int r = row0 + ar0 + mi * 16 + g + h * 8;
                if (r < NNODES) {
#pragma unroll
                    for (int ni = 0; ni < 2; ni++) {
                        int c = nc2 + ni * 8 + tg * 2;
                        *(float2*)&g_h2[(size_t)r * 64 + c] =
                            make_float2(acc[mi][ni][h * 2], acc[mi][ni][h * 2 + 1]);
                    }
                }
            }
    }
}

// ---------------- agg2: half-warp per node ----------------
__global__ void __launch_bounds__(256) agg2_kernel(const float* __restrict__ b2,
                                                   float* __restrict__ out) {
    int t = blockIdx.x * blockDim.x + threadIdx.x;
    int hw = t >> 4;
    int sub = t & 15;
    if (hw >= NNODES) return;
    int beg = g_rowptr[hw], end = g_rowptr[hw + 1];
    float di = g_dinv[hw];
    float d2 = di * di;
    const float4* h2 = (const float4*)g_h2;
    float4 acc = h2[(size_t)hw * 16 + sub];
    acc.x *= d2; acc.y *= d2; acc.z *= d2; acc.w *= d2;
    int j = beg;
    for (; j + 4 <= end; j += 4) {
        int s0 = g_esrc[j], s1 = g_esrc[j + 1], s2 = g_esrc[j + 2], s3 = g_esrc[j + 3];
        float n0 = g_enorm[j], n1 = g_enorm[j + 1], n2 = g_enorm[j + 2], n3 = g_enorm[j + 3];
        float4 v0 = h2[(size_t)s0 * 16 + sub];
        float4 v1 = h2[(size_t)s1 * 16 + sub];
        float4 v2 = h2[(size_t)s2 * 16 + sub];
        float4 v3 = h2[(size_t)s3 * 16 + sub];
        acc.x += v0.x * n0 + v1.x * n1 + v2.x * n2 + v3.x * n3;
        acc.y += v0.y * n0 + v1.y * n1 + v2.y * n2 + v3.y * n3;
        acc.z += v0.z * n0 + v1.z * n1 + v2.z * n2 + v3.z * n3;
        acc.w += v0.w * n0 + v1.w * n1 + v2.w * n2 + v3.w * n3;
    }
    for (; j < end; j++) {
        int s0 = g_esrc[j];
        float n0 = g_enorm[j];
        float4 v0 = h2[(size_t)s0 * 16 + sub];
        acc.x += v0.x * n0; acc.y += v0.y * n0; acc.z += v0.z * n0; acc.w += v0.w * n0;
    }
    float4 bv = ((const float4*)b2)[sub];
    ((float4*)out)[(size_t)hw * 16 + sub] =
        make_float4(acc.x + bv.x, acc.y + bv.y, acc.z + bv.z, acc.w + bv.w);
}

// ---------------- launch ----------------
extern "C" void kernel_launch(void* const* d_in, const int* in_sizes, int n_in,
                              void* d_out, int out_size) {
    const float* x     = (const float*)d_in[0];
    const void*  ei    = d_in[1];
    const float* W1    = (const float*)d_in[2];
    const float* b1    = (const float*)d_in[3];
    const float* gamma = (const float*)d_in[4];
    const float* beta  = (const float*)d_in[5];
    const float* rmean = (const float*)d_in[6];
    const float* rvar  = (const float*)d_in[7];
    const float* W2    = (const float*)d_in[8];
    const float* b2    = (const float*)d_in[9];
    float* out = (float*)d_out;

    const int E = in_sizes[1] / 2;

    cudaFuncSetAttribute(fused_kernel, cudaFuncAttributeMaxDynamicSharedMemorySize, SMF_TOTAL);

    int nblk = (NNODES + 255) / 256;  // 391
    initw_kernel<<<nblk, 256>>>(ei, W1, W2);
    deg_count_kernel<<<(E + 255) / 256, 256>>>(ei, E);
    dinv_scan1_kernel<<<nblk, 256>>>(b1, gamma, beta, rmean, rvar);
    scan2_kernel<<<1, 512>>>(nblk);
    scan3_kernel<<<nblk, 256>>>(E);
    permute_kernel<<<(E + 255) / 256, 256>>>(ei, E);

    int gblk = (NNODES + 127) / 128;  // 782
    fused_kernel<<<gblk, 512, SMF_TOTAL>>>(x);

    {
        long long th = (long long)NNODES * 16;
        agg2_kernel<<<(int)((th + 255) / 256), 256>>>(b2, out);
    }
}